// round 13
// baseline (speedup 1.0000x reference)
#include <cuda_runtime.h>
#include <cuda_bf16.h>
#include <cuda_fp16.h>
#include <cstdint>
#include <math.h>

#define CB 4
#define CS 2048
#define CD 512
#define CH 8
#define CDK 64
#define CM (CB*CS)      // 8192
#define CBH (CB*CH)     // 32
#define CDP (CD/2)      // 256 pairs per D row
#define CSP (CS/2)      // 1024 pairs per score row

// P stored as exp(2x) * 2^-8 (fp16); V stored as v * ci * 2^8 (fp16 split).
#define PSCALE (1.0f/256.0f)
#define VSCALE 256.0f

// Pair-index permutation (4x4 transpose within each aligned 16-pair group).
// Applied identically to P columns and V^T columns; PV sums over t so any
// consistent permutation is exact.
__device__ __forceinline__ uint32_t pperm(uint32_t p) {
    return (p & ~15u) | ((p & 3u) << 2) | ((p >> 2) & 3u);
}

// ---------------- scratch (device globals: allocation-free) ----------------
static __device__ uint2 g_xqp[CM*CDP];                // LN(xq) packed bf16 split
static __device__ uint2 g_xkp[CM*CDP];                // LN(xk) packed bf16 split
static __device__ uint2 g_wp[5][CD*CDP];              // weights packed bf16 split
static __device__ uint2 g_qp[CM*CDP];                 // q/8 packed bf16 split
static __device__ uint2 g_kp[CM*CDP];                 // k packed bf16 split
static __device__ float g_v[CM*CD];
static __device__ float g_gate[CM*CD];
static __device__ uint2 g_aop[CM*CDP];                // attn-out*ri*gate packed bf16 split
static __device__ uint32_t g_p[(size_t)CBH*CS*CSP];   // fp16x2: exp(2x)*2^-8 (perm layout)
static __device__ uint2 g_vtp[CBH*CDK*CSP];           // fp16 split: V^T*ci*2^8 (perm layout)
static __device__ float g_rpart[(size_t)CBH*CS*64];
static __device__ float g_cpart[(size_t)CBH*CS*32];
static __device__ float g_rsum[CBH*CS];
static __device__ float g_csum[CBH*CS];

// ---------------- helpers ----------------
__device__ __forceinline__ uint32_t s2u(const void* p) {
    return (uint32_t)__cvta_generic_to_shared(p);
}
__device__ __forceinline__ void split2(float x0, float x1, uint32_t &hi, uint32_t &lo) {
    __nv_bfloat16 h0 = __float2bfloat16_rn(x0);
    __nv_bfloat16 h1 = __float2bfloat16_rn(x1);
    float r0 = x0 - __bfloat162float(h0);
    float r1 = x1 - __bfloat162float(h1);
    __nv_bfloat16 l0 = __float2bfloat16_rn(r0);
    __nv_bfloat16 l1 = __float2bfloat16_rn(r1);
    hi = (uint32_t)__bfloat16_as_ushort(h0) | ((uint32_t)__bfloat16_as_ushort(h1) << 16);
    lo = (uint32_t)__bfloat16_as_ushort(l0) | ((uint32_t)__bfloat16_as_ushort(l1) << 16);
}
__device__ __forceinline__ uint32_t pack_h2(float x0, float x1) {
    __half2 h = __floats2half2_rn(x0, x1);
    return *(uint32_t*)&h;
}
__device__ __forceinline__ void splith2(float x0, float x1, uint32_t &hi, uint32_t &lo) {
    __half h0 = __float2half_rn(x0);
    __half h1 = __float2half_rn(x1);
    float r0 = x0 - __half2float(h0);
    float r1 = x1 - __half2float(h1);
    __half l0 = __float2half_rn(r0);
    __half l1 = __float2half_rn(r1);
    hi = (uint32_t)__half_as_ushort(h0) | ((uint32_t)__half_as_ushort(h1) << 16);
    lo = (uint32_t)__half_as_ushort(l0) | ((uint32_t)__half_as_ushort(l1) << 16);
}
__device__ __forceinline__ void mma16(float &c0, float &c1, float &c2, float &c3,
                                      uint32_t a0, uint32_t a1, uint32_t a2, uint32_t a3,
                                      uint32_t b0, uint32_t b1) {
    asm("mma.sync.aligned.m16n8k16.row.col.f32.bf16.bf16.f32 "
        "{%0,%1,%2,%3}, {%4,%5,%6,%7}, {%8,%9}, {%0,%1,%2,%3};"
        : "+f"(c0), "+f"(c1), "+f"(c2), "+f"(c3)
        : "r"(a0), "r"(a1), "r"(a2), "r"(a3), "r"(b0), "r"(b1));
}
__device__ __forceinline__ void mma16h(float &c0, float &c1, float &c2, float &c3,
                                       uint32_t a0, uint32_t a1, uint32_t a2, uint32_t a3,
                                       uint32_t b0, uint32_t b1) {
    asm("mma.sync.aligned.m16n8k16.row.col.f32.f16.f16.f32 "
        "{%0,%1,%2,%3}, {%4,%5,%6,%7}, {%8,%9}, {%0,%1,%2,%3};"
        : "+f"(c0), "+f"(c1), "+f"(c2), "+f"(c3)
        : "r"(a0), "r"(a1), "r"(a2), "r"(a3), "r"(b0), "r"(b1));
}
__device__ __forceinline__ void ldsm4(uint32_t &r0, uint32_t &r1, uint32_t &r2, uint32_t &r3,
                                      uint32_t addr) {
    asm volatile("ldmatrix.sync.aligned.m8n8.x4.shared.b16 {%0,%1,%2,%3}, [%4];"
                 : "=r"(r0), "=r"(r1), "=r"(r2), "=r"(r3) : "r"(addr));
}
#define RS 12   // SMEM row stride in uint32 (48B, conflict-free)

__device__ __forceinline__ float fast_exp(float x) {
    x = fmaxf(x, -80.0f);
    float t  = x * 1.4426950408889634f;
    float fi = floorf(t);
    float f  = t - fi;
    float p  = 1.53533e-4f;
    p = fmaf(p, f, 1.33989e-3f);
    p = fmaf(p, f, 9.61844e-3f);
    p = fmaf(p, f, 5.55033e-2f);
    p = fmaf(p, f, 2.40226e-1f);
    p = fmaf(p, f, 6.93147e-1f);
    p = fmaf(p, f, 1.0f);
    return __int_as_float(((int)fi + 127) << 23) * p;
}

// ---------------- LayerNorm -> packed split ----------------
__global__ __launch_bounds__(256)
void ln_kernel(const float* __restrict__ xq, const float* __restrict__ xk,
               const float* __restrict__ gamma, const float* __restrict__ beta)
{
    int row = blockIdx.x;
    const float* x; uint2* o;
    if (row < CM) { x = xq + (size_t)row*CD;       o = g_xqp + (size_t)row*CDP; }
    else          { x = xk + (size_t)(row-CM)*CD;  o = g_xkp + (size_t)(row-CM)*CDP; }
    int t = threadIdx.x;
    float2 v2 = ((const float2*)x)[t];
    float s  = v2.x + v2.y;
    float ss = v2.x*v2.x + v2.y*v2.y;
    #pragma unroll
    for (int off = 16; off; off >>= 1) {
        s  += __shfl_xor_sync(0xffffffffu, s,  off);
        ss += __shfl_xor_sync(0xffffffffu, ss, off);
    }
    __shared__ float sh_s[8], sh_ss[8];
    __shared__ float s_mean, s_rstd;
    int wid = t >> 5, lid = t & 31;
    if (lid == 0) { sh_s[wid] = s; sh_ss[wid] = ss; }
    __syncthreads();
    if (t < 32) {
        float a = (t < 8) ? sh_s[t]  : 0.f;
        float b = (t < 8) ? sh_ss[t] : 0.f;
        #pragma unroll
        for (int off = 4; off; off >>= 1) {
            a += __shfl_xor_sync(0xffffffffu, a, off);
            b += __shfl_xor_sync(0xffffffffu, b, off);
        }
        if (t == 0) {
            float mean = a * (1.0f/CD);
            float var  = b * (1.0f/CD) - mean*mean;
            s_mean = mean;
            s_rstd = rsqrtf(var + 1e-6f);
        }
    }
    __syncthreads();
    float mean = s_mean, rstd = s_rstd;
    float2 g2 = ((const float2*)gamma)[t];
    float2 b2 = ((const float2*)beta)[t];
    float o0 = (v2.x - mean) * rstd * g2.x + b2.x;
    float o1 = (v2.y - mean) * rstd * g2.y + b2.y;
    uint2 pk;
    split2(o0, o1, pk.x, pk.y);
    o[t] = pk;
}

// ---------------- weight split ----------------
__global__ __launch_bounds__(256)
void wsplit_kernel(const float* __restrict__ Wq, const float* __restrict__ Wk,
                   const float* __restrict__ Wv, const float* __restrict__ Wg,
                   const float* __restrict__ Wo)
{
    int m = blockIdx.y;
    const float* W = (m == 0) ? Wq : (m == 1) ? Wk : (m == 2) ? Wv : (m == 3) ? Wg : Wo;
    int idx = blockIdx.x * 256 + threadIdx.x;
    float2 v = ((const float2*)W)[idx];
    uint2 pk;
    split2(v.x, v.y, pk.x, pk.y);
    g_wp[m][idx] = pk;
}

// ---------------- merged projections (packed operands) ----------------------
__global__ __launch_bounds__(256, 2)
void proj_all(const float* __restrict__ bg)
{
    __shared__ uint32_t Ah[2][128][RS], Al[2][128][RS];
    __shared__ uint32_t Bh[2][128][RS], Bl[2][128][RS];
    int mode = blockIdx.z;
    const uint2* A = (mode == 0 || mode == 3) ? g_xqp : g_xkp;
    const uint2* B = g_wp[mode];
    float scale = (mode == 0) ? 0.125f : 1.0f;

    int tid = threadIdx.x, wid = tid >> 5, lane = tid & 31;
    int wm = wid & 1, wn = wid >> 1;
    int m0 = blockIdx.y * 128, n0 = blockIdx.x * 128;
    const uint2* Ag = A + (size_t)m0 * CDP;
    const uint2* Bg = B + (size_t)n0 * CDP;
    int lr = tid >> 2, kp = (tid & 3) * 2;
    int qr = lane >> 2, qc = lane & 3;

    const uint32_t BUF = 128*RS*4;
    uint32_t aAh = s2u(Ah), aAl = s2u(Al), aBh = s2u(Bh), aBl = s2u(Bl);
    uint32_t offA = (uint32_t)(lane & 15) * (RS*4) + (uint32_t)((lane >> 4) & 1) * 16;
    uint32_t offB = (uint32_t)((lane & 7) + ((lane >> 4) & 1) * 8) * (RS*4)
                  + (uint32_t)((lane >> 3) & 1) * 16;

    float acc[4][4][4];
    #pragma unroll
    for (int i = 0; i < 4; i++)
        #pragma unroll
        for (int j = 0; j < 4; j++)
            #pragma unroll
            for (int e = 0; e < 4; e++) acc[i][j][e] = 0.f;

    uint4 rA0, rA1, rB0, rB1;
    #define GLOAD(c) do { \
        size_t o0_ = (size_t)lr*CDP + (size_t)(c)*8 + kp; \
        size_t o1_ = (size_t)(lr+64)*CDP + (size_t)(c)*8 + kp; \
        rA0 = *(const uint4*)(Ag + o0_); rA1 = *(const uint4*)(Ag + o1_); \
        rB0 = *(const uint4*)(Bg + o0_); rB1 = *(const uint4*)(Bg + o1_); \
    } while (0)
    #define GSTAGE(bi) do { \
        *(uint2*)&Ah[bi][lr][kp]    = make_uint2(rA0.x, rA0.z); \
        *(uint2*)&Al[bi][lr][kp]    = make_uint2(rA0.y, rA0.w); \
        *(uint2*)&Ah[bi][lr+64][kp] = make_uint2(rA1.x, rA1.z); \
        *(uint2*)&Al[bi][lr+64][kp] = make_uint2(rA1.y, rA1.w); \
        *(uint2*)&Bh[bi][lr][kp]    = make_uint2(rB0.x, rB0.z); \
        *(uint2*)&Bl[bi][lr][kp]    = make_uint2(rB0.y, rB0.w); \
        *(uint2*)&Bh[bi][lr+64][kp] = make_uint2(rB1.x, rB1.z); \
        *(uint2*)&Bl[bi][lr+64][kp] = make_uint2(rB1.y, rB1.w); \
    } while (0)

    const int NC = CD / 16;    // 32
    GLOAD(0); GSTAGE(0); GLOAD(1);
    __syncthreads();

    for (int c = 0; c < NC; c++) {
        uint32_t cb = (uint32_t)(c & 1) * BUF;
        uint32_t bh[4][2], bl[4][2];
        #pragma unroll
        for (int ntp = 0; ntp < 2; ntp++) {
            uint32_t nbase = (uint32_t)(wn*32 + ntp*16) * (RS*4);
            ldsm4(bh[2*ntp][0], bh[2*ntp][1], bh[2*ntp+1][0], bh[2*ntp+1][1], aBh + cb + nbase + offB);
            ldsm4(bl[2*ntp][0], bl[2*ntp][1], bl[2*ntp+1][0], bl[2*ntp+1][1], aBl + cb + nbase + offB);
        }
        #pragma unroll
        for (int mt = 0; mt < 4; mt++) {
            uint32_t rbase = (uint32_t)(wm*64 + mt*16) * (RS*4);
            uint32_t ah0, ah1, ah2, ah3, al0, al1, al2, al3;
            ldsm4(ah0, ah1, ah2, ah3, aAh + cb + rbase + offA);
            ldsm4(al0, al1, al2, al3, aAl + cb + rbase + offA);
            #pragma unroll
            for (int nt = 0; nt < 4; nt++) {
                mma16(acc[mt][nt][0], acc[mt][nt][1], acc[mt][nt][2], acc[mt][nt][3],
                      ah0, ah1, ah2, ah3, bh[nt][0], bh[nt][1]);
                mma16(acc[mt][nt][0], acc[mt][nt][1], acc[mt][nt][2], acc[mt][nt][3],
                      ah0, ah1, ah2, ah3, bl[nt][0], bl[nt][1]);
                mma16(acc[mt][nt][0], acc[mt][nt][1], acc[mt][nt][2], acc[mt][nt][3],
                      al0, al1, al2, al3, bh[nt][0], bh[nt][1]);
            }
        }
        if (c + 1 < NC) {
            GSTAGE((c+1) & 1);
            if (c + 2 < NC) GLOAD(c+2);
        }
        __syncthreads();
    }
    #undef GLOAD
    #undef GSTAGE

    if (mode <= 1) {
        uint2* O = (mode == 0) ? g_qp : g_kp;
        #pragma unroll
        for (int mt = 0; mt < 4; mt++) {
            int r = m0 + wm*64 + mt*16 + qr;
            #pragma unroll
            for (int nt = 0; nt < 4; nt++) {
                int colp = (n0 >> 1) + wn*16 + nt*4 + qc;
                uint2 pk;
                split2(acc[mt][nt][0]*scale, acc[mt][nt][1]*scale, pk.x, pk.y);
                O[(size_t)r*CDP + colp] = pk;
                split2(acc[mt][nt][2]*scale, acc[mt][nt][3]*scale, pk.x, pk.y);
                O[(size_t)(r+8)*CDP + colp] = pk;
            }
        }
    } else {
        float* O = (mode == 2) ? g_v : g_gate;
        #pragma unroll
        for (int mt = 0; mt < 4; mt++) {
            int r = m0 + wm*64 + mt*16 + qr;
            #pragma unroll
            for (int nt = 0; nt < 4; nt++) {
                int col = n0 + wn*32 + nt*8 + qc*2;
                float o0 = acc[mt][nt][0], o1 = acc[mt][nt][1];
                float o2 = acc[mt][nt][2], o3 = acc[mt][nt][3];
                if (mode == 3) {
                    float b0 = bg[col], b1 = bg[col+1];
                    o0 = 1.0f/(1.0f + __expf(-(o0+b0)));
                    o1 = 1.0f/(1.0f + __expf(-(o1+b1)));
                    o2 = 1.0f/(1.0f + __expf(-(o2+b0)));
                    o3 = 1.0f/(1.0f + __expf(-(o3+b1)));
                }
                *(float2*)(O + (size_t)r*CD + col)     = make_float2(o0, o1);
                *(float2*)(O + (size_t)(r+8)*CD + col) = make_float2(o2, o3);
            }
        }
    }
}

// ---------------- scores + stats (fp16 exp out, permuted vectorized) --------
__global__ __launch_bounds__(256, 2)
void scores_stats()
{
    __shared__ uint32_t Ah[2][128][RS], Al[2][128][RS];
    __shared__ uint32_t Bh[2][128][RS], Bl[2][128][RS];
    int z = blockIdx.z, b = z >> 3, h = z & 7;
    int m0 = blockIdx.y * 128, n0 = blockIdx.x * 128;
    int tid = threadIdx.x, wid = tid >> 5, lane = tid & 31;
    int wm = wid & 1, wn = wid >> 1;
    int lr = tid >> 2, kp = (tid & 3) * 2;
    int qr = lane >> 2, qc = lane & 3;

    const uint2* Ag = g_qp + (size_t)(b*CS + m0)*CDP + h*32;
    const uint2* Bg = g_kp + (size_t)(b*CS + n0)*CDP + h*32;

    const uint32_t BUF = 128*RS*4;
    uint32_t aAh = s2u(Ah), aAl = s2u(Al), aBh = s2u(Bh), aBl = s2u(Bl);
    uint32_t offA = (uint32_t)(lane & 15) * (RS*4) + (uint32_t)((lane >> 4) & 1) * 16;
    uint32_t offB = (uint32_t)((lane & 7) + ((lane >> 4) & 1) * 8) * (RS*4)
                  + (uint32_t)((lane >> 3) & 1) * 16;

    float acc[4][4][4];
    #pragma unroll
    for (int i = 0; i < 4; i++)
        #pragma unroll
        for (int j = 0; j < 4; j++)
            #pragma unroll
            for (int e = 0; e < 4; e++) acc[i][j][e] = 0.f;

    uint4 rA0, rA1, rB0, rB1;
    #define SLOAD(c) do { \
        size_t o0_ = (size_t)lr*CDP + (size_t)(c)*8 + kp; \
        size_t o1_ = (size_t)(lr+64)*CDP + (size_t)(c)*8 + kp; \
        rA0 = *(const uint4*)(Ag + o0_); rA1 = *(const uint4*)(Ag + o1_); \
        rB0 = *(const uint4*)(Bg + o0_); rB1 = *(const uint4*)(Bg + o1_); \
    } while (0)
    #define SSTAGE(bi) do { \
        *(uint2*)&Ah[bi][lr][kp]    = make_uint2(rA0.x, rA0.z); \
        *(uint2*)&Al[bi][lr][kp]    = make_uint2(rA0.y, rA0.w); \
        *(uint2*)&Ah[bi][lr+64][kp] = make_uint2(rA1.x, rA1.z); \
        *(uint2*)&Al[bi][lr+64][kp] = make_uint2(rA1.y, rA1.w); \
        *(uint2*)&Bh[bi][lr][kp]    = make_uint2(rB0.x, rB0.z); \
        *(uint2*)&Bl[bi][lr][kp]    = make_uint2(rB0.y, rB0.w); \
        *(uint2*)&Bh[bi][lr+64][kp] = make_uint2(rB1.x, rB1.z); \
        *(uint2*)&Bl[bi][lr+64][kp] = make_uint2(rB1.y, rB1.w); \
    } while (0)

    const int NC = CDK / 16;   // 4
    SLOAD(0); SSTAGE(0); SLOAD(1);
    __syncthreads();

    for (int c = 0; c < NC; c++) {
        uint32_t cb = (uint32_t)(c & 1) * BUF;
        uint32_t bh[4][2], bl[4][2];
        #pragma unroll
        for (int ntp = 0; ntp < 2; ntp++) {
            uint32_t nbase = (uint32_t)(wn*32 + ntp*16) * (RS*4);
            ldsm4(bh[2*ntp][0], bh[2*ntp][1], bh[2*ntp+1][0], bh[2*ntp+1][1], aBh + cb + nbase + offB);
            ldsm4(bl[2*ntp][0], bl[2*ntp][1], bl[2*ntp+1][0], bl[2*ntp+1][1], aBl + cb + nbase + offB);
        }
        #pragma unroll
        for (int mt = 0; mt < 4; mt++) {
            uint32_t rbase = (uint32_t)(wm*64 + mt*16) * (RS*4);
            uint32_t ah0, ah1, ah2, ah3, al0, al1, al2, al3;
            ldsm4(ah0, ah1, ah2, ah3, aAh + cb + rbase + offA);
            ldsm4(al0, al1, al2, al3, aAl + cb + rbase + offA);
            #pragma unroll
            for (int nt = 0; nt < 4; nt++) {
                mma16(acc[mt][nt][0], acc[mt][nt][1], acc[mt][nt][2], acc[mt][nt][3],
                      ah0, ah1, ah2, ah3, bh[nt][0], bh[nt][1]);
                mma16(acc[mt][nt][0], acc[mt][nt][1], acc[mt][nt][2], acc[mt][nt][3],
                      ah0, ah1, ah2, ah3, bl[nt][0], bl[nt][1]);
                mma16(acc[mt][nt][0], acc[mt][nt][1], acc[mt][nt][2], acc[mt][nt][3],
                      al0, al1, al2, al3, bh[nt][0], bh[nt][1]);
            }
        }
        if (c + 1 < NC) {
            SSTAGE((c+1) & 1);
            if (c + 2 < NC) SLOAD(c+2);
        }
        __syncthreads();
    }
    #undef SLOAD
    #undef SSTAGE

    // epilogue: ex = exp(x); stats partials; permuted uint4 P stores
    float csl[4][2];
    #pragma unroll
    for (int nt = 0; nt < 4; nt++) { csl[nt][0] = 0.f; csl[nt][1] = 0.f; }
    #pragma unroll
    for (int mt = 0; mt < 4; mt++) {
        float ex[4][4];
        #pragma unroll
        for (int nt = 0; nt < 4; nt++)
            #pragma unroll
            for (int e = 0; e < 4; e++) ex[nt][e] = fast_exp(acc[mt][nt][e]);
        float r0 = 0.f, r1 = 0.f;
        #pragma unroll
        for (int nt = 0; nt < 4; nt++) {
            r0 += ex[nt][0] + ex[nt][1];
            r1 += ex[nt][2] + ex[nt][3];
            csl[nt][0] += ex[nt][0] + ex[nt][2];
            csl[nt][1] += ex[nt][1] + ex[nt][3];
        }
        r0 += __shfl_xor_sync(0xffffffffu, r0, 1);
        r0 += __shfl_xor_sync(0xffffffffu, r0, 2);
        r1 += __shfl_xor_sync(0xffffffffu, r1, 1);
        r1 += __shfl_xor_sync(0xffffffffu, r1, 2);
        int row0 = m0 + wm*64 + mt*16 + qr;
        if (qc == 0) {
            int rslot = blockIdx.x * 4 + wn;
            g_rpart[((size_t)(z*CS + row0) << 6) + rslot]     = r0;
            g_rpart[((size_t)(z*CS + row0 + 8) << 6) + rslot] = r1;
        }
        // permuted pair layout: thread's 4 pairs contiguous at qc*4 + nt
        {
            int pb = (n0 >> 1) + wn*16 + qc*4;
            uint4 u0, u1;
            u0.x = pack_h2(ex[0][0]*ex[0][0]*PSCALE, ex[0][1]*ex[0][1]*PSCALE);
            u0.y = pack_h2(ex[1][0]*ex[1][0]*PSCALE, ex[1][1]*ex[1][1]*PSCALE);
            u0.z = pack_h2(ex[2][0]*ex[2][0]*PSCALE, ex[2][1]*ex[2][1]*PSCALE);
            u0.w = pack_h2(ex[3][0]*ex[3][0]*PSCALE, ex[3][1]*ex[3][1]*PSCALE);
            u1.x = pack_h2(ex[0][2]*ex[0][2]*PSCALE, ex[0][3]*ex[0][3]*PSCALE);
            u1.y = pack_h2(ex[1][2]*ex[1][2]*PSCALE, ex[1][3]*ex[1][3]*PSCALE);
            u1.z = pack_h2(ex[2][2]*ex[2][2]*PSCALE, ex[2][3]*ex[2][3]*PSCALE);
            u1.w = pack_h2(ex[3][2]*ex[3][2]*PSCALE, ex[3][3]*ex[3][3]*PSCALE);
            *(uint4*)(g_p + (size_t)(z*CS + row0)*CSP + pb)     = u0;
            *(uint4*)(g_p + (size_t)(z*CS + row0 + 8)*CSP + pb) = u1;
        }
    }
    #pragma unroll
    for (int nt = 0; nt < 4; nt++) {
        #pragma unroll
        for (int j = 0; j < 2; j++) {
            float v = csl[nt][j];
            v += __shfl_xor_sync(0xffffffffu, v, 4);
            v += __shfl_xor_sync(0xffffffffu, v, 8);
            v += __shfl_xor_sync(0xffffffffu, v, 16);
            if (qr == 0) {
                int cslot = blockIdx.y * 2 + wm;
                int col = n0 + wn*32 + nt*8 + qc*2 + j;
                g_cpart[((size_t)(z*CS + col) << 5) + cslot] = v;
            }
        }
    }
}

// ---------------- finalize: reduce partials -> reciprocals ------------------
__global__ __launch_bounds__(256)
void finalize_kernel()
{
    int i = blockIdx.x * 256 + threadIdx.x;
    if (i < CBH*CS) {
        const float4* p = (const float4*)(g_rpart + ((size_t)i << 6));
        float s = 0.f;
        #pragma unroll
        for (int j = 0; j < 16; j++) {
            float4 v = p[j];
            s += v.x + v.y + v.z + v.w;
        }
        g_rsum[i] = 1.0f / s;
    } else {
        i -= CBH*CS;
        const float4* p = (const float4*)(g_cpart + ((size_t)i << 5));
        float s = 0.f;
        #pragma unroll
        for (int j = 0; j < 8; j++) {
            float4 v = p[j];
            s += v.x + v.y + v.z + v.w;
        }
        g_csum[i] = 1.0f / s;
    }
}

// ---------------- V transpose: ci*256 folded, fp16 split, permuted ----------
__global__ __launch_bounds__(256)
void vtrans_ci()
{
    __shared__ float tile[64][65];
    int z = blockIdx.y, b = z >> 3, h = z & 7;
    int t0 = blockIdx.x * 64;
    const float* src = g_v + (size_t)b*CS*CD + h*CDK;
    int tid = threadIdx.x;
    #pragma unroll
    for (int i = 0; i < 16; i++) {
        int idx = tid + i*256;
        int tr = idx >> 6, d = idx & 63;
        tile[tr][d] = src[(size_t)(t0 + tr)*CD + d] * (g_csum[z*CS + t0 + tr] * VSCALE);
    }
    __syncthreads();
    #pragma unroll
    for (int i = 0; i < 8; i++) {
        int idx = tid + i*256;
        int d = idx >> 5, tp = idx & 31;
        uint2 pk;
        splith2(tile[2*tp][d], tile[2*tp+1][d], pk.x, pk.y);
        uint32_t p = pperm((uint32_t)((t0 >> 1) + tp));
        g_vtp[((size_t)z*CDK + d)*CSP + p] = pk;
    }
}

// ---------------- PV: fp16 P (single) x fp16 V (split), packed out ----------
__global__ __launch_bounds__(256)
void pv_kernel()
{
    __shared__ uint32_t Ph[2][128][RS];
    __shared__ uint32_t Vh[2][64][RS], Vl[2][64][RS];
    int z = blockIdx.y, b = z >> 3, h = z & 7;
    int s0 = blockIdx.x * 128;
    int tid = threadIdx.x, wid = tid >> 5, lane = tid & 31;
    int wm = wid & 3, wn = wid >> 2;
    int qr = lane >> 2, qc = lane & 3;

    int pr = tid >> 1;                 // P row 0..127
    int pp = (tid & 1) * 4;            // uint32 base 0/4 within 8-u32 chunk row
    int vr = tid >> 2;                 // V^T row (dk) 0..63
    int vp = (tid & 3) * 2;            // pair base 0,2,4,6
    const uint32_t* aph = g_p   + (size_t)(z*CS + s0 + pr)*CSP;
    const uint2*    avh = g_vtp + ((size_t)z*CDK + vr)*CSP;

    const uint32_t BUFP = 128*RS*4, BUFV = 64*RS*4;
    uint32_t aPh = s2u(Ph), aVh = s2u(Vh), aVl = s2u(Vl);
    uint32_t offA = (uint32_t)(lane & 15) * (RS*4) + (uint32_t)((lane >> 4) & 1) * 16;
    uint32_t offB = (uint32_t)((lane & 7) + ((lane >> 4) & 1) * 8) * (RS*4)
                  + (uint32_t)((lane >> 3) & 1) * 16;

    float acc[2][4][4];
    #pragma unroll
    for (int i = 0; i < 2; i++)
        #pragma unroll
        for (int j = 0; j < 4; j++)
            #pragma unroll
            for (int e = 0; e < 4; e++) acc[i][j][e] = 0.f;

    uint4 rp0, rv0;
    #define PLOAD(c) do { \
        rp0 = *(const uint4*)(aph + (size_t)(c)*8 + pp); \
        rv0 = *(const uint4*)(avh + (size_t)(c)*8 + vp); \
    } while (0)
    #define PSTAGE(bi) do { \
        *(uint4*)&Ph[bi][pr][pp] = rp0; \
        *(uint2*)&Vh[bi][vr][vp] = make_uint2(rv0.x, rv0.z); \
        *(uint2*)&Vl[bi][vr][vp] = make_uint2(rv0.y, rv0.w); \
    } while (0)

    const int NC = CS / 16;            // 128 chunks
    PLOAD(0); PSTAGE(0); PLOAD(1);
    __syncthreads();

    for (int c = 0; c < NC; c++) {
        uint32_t cbP = (uint32_t)(c & 1) * BUFP;
        uint32_t cbV = (uint32_t)(c & 1) * BUFV;
        uint32_t bh[4][2], bl[4][2];
        #pragma unroll
        for (int ntp = 0; ntp < 2; ntp++) {
            uint32_t nbase = (uint32_t)(wn*32 + ntp*16) * (RS*4);
            ldsm4(bh[2*ntp][0], bh[2*ntp][1], bh[2*ntp+1][0], bh[2*ntp+1][1], aVh + cbV + nbase + offB);
            ldsm4(bl[2*ntp][0], bl[2*ntp][1], bl[2*ntp+1][0], bl[2*ntp+1][1], aVl + cbV + nbase + offB);
        }
        #pragma unroll
        for (int mt = 0; mt < 2; mt++) {
            uint32_t rbase = (uint32_t)(wm*32 + mt*16) * (RS*4);
            uint32_t a0, a1, a2, a3;
            ldsm4(a0, a1, a2, a3, aPh + cbP + rbase + offA);
            #pragma unroll
            for (int nt = 0; nt < 4; nt++) {
                mma16h(acc[mt][nt][0], acc[mt][nt][1], acc[mt][nt][2], acc[mt][nt][3],
                       a0, a1, a2, a3, bh[nt][0], bh[nt][1]);
                mma16h(acc[mt][nt][0], acc[mt][nt][1], acc[mt][nt][2], acc[mt][nt][3],
                       a0, a1, a2, a3, bl[nt][0], bl[nt][1]);
            }
        }
        if (c + 1 < NC) {
            PSTAGE((c+1) & 1);
            if (c + 2 < NC) PLOAD(c+2);
        }
        __syncthreads();
    }
    #undef PLOAD
    #undef PSTAGE
    // epilogue: * rsum_inv, * gate -> g_aop (packed bf16 split)
    #pragma unroll
    for (int mt = 0; mt < 2; mt++) {
        #pragma unroll
        for (int half = 0; half < 2; half++) {
            int srow = s0 + wm*32 + mt*16 + qr + half*8;
            float ri = g_rsum[(size_t)z*CS + srow];
            const float* grow = g_gate + ((size_t)b*CS + srow)*CD + h*CDK;
            uint2* orow       = g_aop  + ((size_t)b*CS + srow)*CDP + h*32;
            #pragma unroll
            for (int nt = 0; nt < 4; nt++) {
                int col = wn*32 + nt*8 + qc*2;
                float2 gg = *(const float2*)(grow + col);
                float o0 = acc[mt][nt][half*2+0] * ri * gg.x;
                float o1 = acc[mt][nt][half*2+1] * ri * gg.y;
                uint2 pk;
                split2(o0, o1, pk.x, pk.y);
                orow[col >> 1] = pk;
            }
        }
    }
}

// ---------------- output projection: packed A/B, bias -> d_out --------------
__global__ __launch_bounds__(256, 2)
void out_gemm(const float* __restrict__ bo, float* __restrict__ C)
{
    __shared__ uint32_t Ah[2][128][RS], Al[2][128][RS];
    __shared__ uint32_t Bh[2][128][RS], Bl[2][128][RS];
    int tid = threadIdx.x, wid = tid >> 5, lane = tid & 31;
    int wm = wid & 1, wn = wid >> 1;
    int m0 = blockIdx.y * 128, n0 = blockIdx.x * 128;
    const uint2* Ag = g_aop + (size_t)m0 * CDP;
    const uint2* Bg = g_wp[4] + (size_t)n0 * CDP;
    int lr = tid >> 2, kp = (tid & 3) * 2;
    int qr = lane >> 2, qc = lane & 3;

    const uint32_t BUF = 128*RS*4;
    uint32_t aAh = s2u(Ah), aAl = s2u(Al), aBh = s2u(Bh), aBl = s2u(Bl);
    uint32_t offA = (uint32_t)(lane & 15) * (RS*4) + (uint32_t)((lane >> 4) & 1) * 16;
    uint32_t offB = (uint32_t)((lane & 7) + ((lane >> 4) & 1) * 8) * (RS*4)
                  + (uint32_t)((lane >> 3) & 1) * 16;

    float acc[4][4][4];
    #pragma unroll
    for (int i = 0; i < 4; i++)
        #pragma unroll
        for (int j = 0; j < 4; j++)
            #pragma unroll
            for (int e = 0; e < 4; e++) acc[i][j][e] = 0.f;

    uint4 rA0, rA1, rB0, rB1;
    #define OLOAD(c) do { \
        size_t o0_ = (size_t)lr*CDP + (size_t)(c)*8 + kp; \
        size_t o1_ = (size_t)(lr+64)*CDP + (size_t)(c)*8 + kp; \
        rA0 = *(const uint4*)(Ag + o0_); rA1 = *(const uint4*)(Ag + o1_); \
        rB0 = *(const uint4*)(Bg + o0_); rB1 = *(const uint4*)(Bg + o1_); \
    } while (0)
    #define OSTAGE(bi) do { \
        *(uint2*)&Ah[bi][lr][kp]    = make_uint2(rA0.x, rA0.z); \
        *(uint2*)&Al[bi][lr][kp]    = make_uint2(rA0.y, rA0.w); \
        *(uint2*)&Ah[bi][lr+64][kp] = make_uint2(rA1.x, rA1.z); \
        *(uint2*)&Al[bi][lr+64][kp] = make_uint2(rA1.y, rA1.w); \
        *(uint2*)&Bh[bi][lr][kp]    = make_uint2(rB0.x, rB0.z); \
        *(uint2*)&Bl[bi][lr][kp]    = make_uint2(rB0.y, rB0.w); \
        *(uint2*)&Bh[bi][lr+64][kp] = make_uint2(rB1.x, rB1.z); \
        *(uint2*)&Bl[bi][lr+64][kp] = make_uint2(rB1.y, rB1.w); \
    } while (0)

    const int NC = CD / 16;
    OLOAD(0); OSTAGE(0); OLOAD(1);
    __syncthreads();

    for (int c = 0; c < NC; c++) {
        uint32_t cb = (uint32_t)(c & 1) * BUF;
        uint32_t bh[4][2], bl[4][2];
        #pragma unroll
        for (int ntp = 0; ntp < 2; ntp++) {
            uint32_t nbase = (uint32_t)(wn*32 + ntp*16) * (RS*4);
            ldsm4(bh[2*ntp][0], bh[2*ntp][1], bh[2*ntp+1][0], bh[2*ntp+1][1], aBh + cb + nbase + offB);
            ldsm4(bl[2*ntp][0], bl[2*ntp][1], bl[2*ntp+1][0], bl[2*ntp+1][1], aBl + cb + nbase + offB);
        }
        #pragma unroll
        for (int mt = 0; mt < 4; mt++) {
            uint32_t rbase = (uint32_t)(wm*64 + mt*16) * (RS*4);
            uint32_t ah0, ah1, ah2, ah3, al0, al1, al2, al3;
            ldsm4(ah0, ah1, ah2, ah3, aAh + cb + rbase + offA);
            ldsm4(al0, al1, al2, al3, aAl + cb + rbase + offA);
            #pragma unroll
            for (int nt = 0; nt < 4; nt++) {
                mma16(acc[mt][nt][0], acc[mt][nt][1], acc[mt][nt][2], acc[mt][nt][3],
                      ah0, ah1, ah2, ah3, bh[nt][0], bh[nt][1]);
                mma16(acc[mt][nt][0], acc[mt][nt][1], acc[mt][nt][2], acc[mt][nt][3],
                      ah0, ah1, ah2, ah3, bl[nt][0], bl[nt][1]);
                mma16(acc[mt][nt][0], acc[mt][nt][1], acc[mt][nt][2], acc[mt][nt][3],
                      al0, al1, al2, al3, bh[nt][0], bh[nt][1]);
            }
        }
        if (c + 1 < NC) {
            OSTAGE((c+1) & 1);
            if (c + 2 < NC) OLOAD(c+2);
        }
        __syncthreads();
    }
    #undef OLOAD
    #undef OSTAGE
    #pragma unroll
    for (int mt = 0; mt < 4; mt++) {
        int r = m0 + wm*64 + mt*16 + qr;
        #pragma unroll
        for (int nt = 0; nt < 4; nt++) {
            int col = n0 + wn*32 + nt*8 + qc*2;
            float b0 = bo[col], b1 = bo[col+1];
            *(float2*)(C + (size_t)r*CD + col) =
                make_float2(acc[mt][nt][0] + b0, acc[mt][nt][1] + b1);
            *(float2*)(C + (size_t)(r+8)*CD + col) =
                make_float2(acc[mt][nt][2] + b0, acc[mt][nt][3] + b1);
        }
    }
}

// ---------------- launch ----------------
extern "C" void kernel_launch(void* const* d_in, const int* in_sizes, int n_in,
                              void* d_out, int out_size)
{
    const float* x_q   = (const float*)d_in[0];
    const float* x_k   = (const float*)d_in[1];
    const float* Wq    = (const float*)d_in[2];
    const float* Wk    = (const float*)d_in[3];
    const float* Wv    = (const float*)d_in[4];
    const float* Wg    = (const float*)d_in[5];
    const float* bg    = (const float*)d_in[6];
    const float* Wo    = (const float*)d_in[7];
    const float* bo    = (const float*)d_in[8];
    const float* gamma = (const float*)d_in[9];
    const float* beta  = (const float*)d_in[10];
    float* out = (float*)d_out;

    // 1. LayerNorm (packed-split output) + weight split
    ln_kernel<<<2*CM, 256>>>(x_q, x_k, gamma, beta);
    wsplit_kernel<<<dim3(CD*CDP/256, 5), 256>>>(Wq, Wk, Wv, Wg, Wo);

    // 2. All projections, one launch (copy-staged)
    proj_all<<<dim3(CD/128, CM/128, 4), 256>>>(bg);

    // 3. Scores + stats, fp16 exp(2x)*2^-8, permuted vectorized stores
    scores_stats<<<dim3(CS/128, CS/128, CBH), 256>>>();

    // 4. Reduce partials -> reciprocal sums
    finalize_kernel<<<(2*CBH*CS)/256, 256>>>();

    // 5. V transpose with ci*256 folded, fp16 split, matching permutation
    vtrans_ci<<<dim3(CS/64, CBH), 256>>>();

    // 6. PV: fp16 MMA (2 per tile), packed bf16 split out
    pv_kernel<<<dim3(CS/128, CBH), 256>>>();

    // 7. Output projection (copy-staged) + bias -> d_out
    out_gemm<<<dim3(CD/128, CM/128), 256>>>(bo, out);
}

// round 14
// speedup vs baseline: 1.4346x; 1.4346x over previous
#include <cuda_runtime.h>
#include <cuda_bf16.h>
#include <cuda_fp16.h>
#include <cstdint>
#include <math.h>

#define CB 4
#define CS 2048
#define CD 512
#define CH 8
#define CDK 64
#define CM (CB*CS)      // 8192
#define CBH (CB*CH)     // 32
#define CDP (CD/2)      // 256 pairs per D row
#define CSP (CS/2)      // 1024 pairs per score row

// P stored as exp(2x) * 2^-8 (fp16); V stored as v * ci * 2^8 (fp16 split).
#define PSCALE (1.0f/256.0f)
#define VSCALE 256.0f

// ---------------- scratch (device globals: allocation-free) ----------------
static __device__ uint2 g_xqp[CM*CDP];                // LN(xq) packed bf16 split
static __device__ uint2 g_xkp[CM*CDP];                // LN(xk) packed bf16 split
static __device__ uint2 g_wp[5][CD*CDP];              // weights packed bf16 split
static __device__ uint2 g_qp[CM*CDP];                 // q/8 packed bf16 split
static __device__ uint2 g_kp[CM*CDP];                 // k packed bf16 split
static __device__ float g_v[CM*CD];
static __device__ float g_gate[CM*CD];
static __device__ uint2 g_aop[CM*CDP];                // attn-out*ri*gate packed bf16 split
static __device__ uint32_t g_p[(size_t)CBH*CS*CSP];   // fp16x2: exp(2x)*2^-8
static __device__ uint2 g_vtp[CBH*CDK*CSP];           // fp16 split: V^T*ci*2^8
static __device__ float g_rpart[(size_t)CBH*CS*64];
static __device__ float g_cpart[(size_t)CBH*CS*32];
static __device__ float g_rsum[CBH*CS];
static __device__ float g_csum[CBH*CS];

// ---------------- helpers ----------------
__device__ __forceinline__ uint32_t s2u(const void* p) {
    return (uint32_t)__cvta_generic_to_shared(p);
}
__device__ __forceinline__ void split2(float x0, float x1, uint32_t &hi, uint32_t &lo) {
    __nv_bfloat16 h0 = __float2bfloat16_rn(x0);
    __nv_bfloat16 h1 = __float2bfloat16_rn(x1);
    float r0 = x0 - __bfloat162float(h0);
    float r1 = x1 - __bfloat162float(h1);
    __nv_bfloat16 l0 = __float2bfloat16_rn(r0);
    __nv_bfloat16 l1 = __float2bfloat16_rn(r1);
    hi = (uint32_t)__bfloat16_as_ushort(h0) | ((uint32_t)__bfloat16_as_ushort(h1) << 16);
    lo = (uint32_t)__bfloat16_as_ushort(l0) | ((uint32_t)__bfloat16_as_ushort(l1) << 16);
}
__device__ __forceinline__ uint32_t pack_h2(float x0, float x1) {
    __half2 h = __floats2half2_rn(x0, x1);
    return *(uint32_t*)&h;
}
__device__ __forceinline__ void splith2(float x0, float x1, uint32_t &hi, uint32_t &lo) {
    __half h0 = __float2half_rn(x0);
    __half h1 = __float2half_rn(x1);
    float r0 = x0 - __half2float(h0);
    float r1 = x1 - __half2float(h1);
    __half l0 = __float2half_rn(r0);
    __half l1 = __float2half_rn(r1);
    hi = (uint32_t)__half_as_ushort(h0) | ((uint32_t)__half_as_ushort(h1) << 16);
    lo = (uint32_t)__half_as_ushort(l0) | ((uint32_t)__half_as_ushort(l1) << 16);
}
__device__ __forceinline__ void mma16(float &c0, float &c1, float &c2, float &c3,
                                      uint32_t a0, uint32_t a1, uint32_t a2, uint32_t a3,
                                      uint32_t b0, uint32_t b1) {
    asm("mma.sync.aligned.m16n8k16.row.col.f32.bf16.bf16.f32 "
        "{%0,%1,%2,%3}, {%4,%5,%6,%7}, {%8,%9}, {%0,%1,%2,%3};"
        : "+f"(c0), "+f"(c1), "+f"(c2), "+f"(c3)
        : "r"(a0), "r"(a1), "r"(a2), "r"(a3), "r"(b0), "r"(b1));
}
__device__ __forceinline__ void mma16h(float &c0, float &c1, float &c2, float &c3,
                                       uint32_t a0, uint32_t a1, uint32_t a2, uint32_t a3,
                                       uint32_t b0, uint32_t b1) {
    asm("mma.sync.aligned.m16n8k16.row.col.f32.f16.f16.f32 "
        "{%0,%1,%2,%3}, {%4,%5,%6,%7}, {%8,%9}, {%0,%1,%2,%3};"
        : "+f"(c0), "+f"(c1), "+f"(c2), "+f"(c3)
        : "r"(a0), "r"(a1), "r"(a2), "r"(a3), "r"(b0), "r"(b1));
}
__device__ __forceinline__ void ldsm4(uint32_t &r0, uint32_t &r1, uint32_t &r2, uint32_t &r3,
                                      uint32_t addr) {
    asm volatile("ldmatrix.sync.aligned.m8n8.x4.shared.b16 {%0,%1,%2,%3}, [%4];"
                 : "=r"(r0), "=r"(r1), "=r"(r2), "=r"(r3) : "r"(addr));
}
#define RS 12   // SMEM row stride in uint32 (48B, conflict-free)

__device__ __forceinline__ float fast_exp(float x) {
    x = fmaxf(x, -80.0f);
    float t  = x * 1.4426950408889634f;
    float fi = floorf(t);
    float f  = t - fi;
    float p  = 1.53533e-4f;
    p = fmaf(p, f, 1.33989e-3f);
    p = fmaf(p, f, 9.61844e-3f);
    p = fmaf(p, f, 5.55033e-2f);
    p = fmaf(p, f, 2.40226e-1f);
    p = fmaf(p, f, 6.93147e-1f);
    p = fmaf(p, f, 1.0f);
    return __int_as_float(((int)fi + 127) << 23) * p;
}

// ---------------- LayerNorm -> packed split ----------------
__global__ __launch_bounds__(256)
void ln_kernel(const float* __restrict__ xq, const float* __restrict__ xk,
               const float* __restrict__ gamma, const float* __restrict__ beta)
{
    int row = blockIdx.x;
    const float* x; uint2* o;
    if (row < CM) { x = xq + (size_t)row*CD;       o = g_xqp + (size_t)row*CDP; }
    else          { x = xk + (size_t)(row-CM)*CD;  o = g_xkp + (size_t)(row-CM)*CDP; }
    int t = threadIdx.x;
    float2 v2 = ((const float2*)x)[t];
    float s  = v2.x + v2.y;
    float ss = v2.x*v2.x + v2.y*v2.y;
    #pragma unroll
    for (int off = 16; off; off >>= 1) {
        s  += __shfl_xor_sync(0xffffffffu, s,  off);
        ss += __shfl_xor_sync(0xffffffffu, ss, off);
    }
    __shared__ float sh_s[8], sh_ss[8];
    __shared__ float s_mean, s_rstd;
    int wid = t >> 5, lid = t & 31;
    if (lid == 0) { sh_s[wid] = s; sh_ss[wid] = ss; }
    __syncthreads();
    if (t < 32) {
        float a = (t < 8) ? sh_s[t]  : 0.f;
        float b = (t < 8) ? sh_ss[t] : 0.f;
        #pragma unroll
        for (int off = 4; off; off >>= 1) {
            a += __shfl_xor_sync(0xffffffffu, a, off);
            b += __shfl_xor_sync(0xffffffffu, b, off);
        }
        if (t == 0) {
            float mean = a * (1.0f/CD);
            float var  = b * (1.0f/CD) - mean*mean;
            s_mean = mean;
            s_rstd = rsqrtf(var + 1e-6f);
        }
    }
    __syncthreads();
    float mean = s_mean, rstd = s_rstd;
    float2 g2 = ((const float2*)gamma)[t];
    float2 b2 = ((const float2*)beta)[t];
    float o0 = (v2.x - mean) * rstd * g2.x + b2.x;
    float o1 = (v2.y - mean) * rstd * g2.y + b2.y;
    uint2 pk;
    split2(o0, o1, pk.x, pk.y);
    o[t] = pk;
}

// ---------------- weight split ----------------
__global__ __launch_bounds__(256)
void wsplit_kernel(const float* __restrict__ Wq, const float* __restrict__ Wk,
                   const float* __restrict__ Wv, const float* __restrict__ Wg,
                   const float* __restrict__ Wo)
{
    int m = blockIdx.y;
    const float* W = (m == 0) ? Wq : (m == 1) ? Wk : (m == 2) ? Wv : (m == 3) ? Wg : Wo;
    int idx = blockIdx.x * 256 + threadIdx.x;
    float2 v = ((const float2*)W)[idx];
    uint2 pk;
    split2(v.x, v.y, pk.x, pk.y);
    g_wp[m][idx] = pk;
}

// ---------------- merged projections (packed operands) ----------------------
__global__ __launch_bounds__(256, 2)
void proj_all(const float* __restrict__ bg)
{
    __shared__ uint32_t Ah[2][128][RS], Al[2][128][RS];
    __shared__ uint32_t Bh[2][128][RS], Bl[2][128][RS];
    int mode = blockIdx.z;
    const uint2* A = (mode == 0 || mode == 3) ? g_xqp : g_xkp;
    const uint2* B = g_wp[mode];
    float scale = (mode == 0) ? 0.125f : 1.0f;

    int tid = threadIdx.x, wid = tid >> 5, lane = tid & 31;
    int wm = wid & 1, wn = wid >> 1;
    int m0 = blockIdx.y * 128, n0 = blockIdx.x * 128;
    const uint2* Ag = A + (size_t)m0 * CDP;
    const uint2* Bg = B + (size_t)n0 * CDP;
    int lr = tid >> 2, kp = (tid & 3) * 2;
    int qr = lane >> 2, qc = lane & 3;

    const uint32_t BUF = 128*RS*4;
    uint32_t aAh = s2u(Ah), aAl = s2u(Al), aBh = s2u(Bh), aBl = s2u(Bl);
    uint32_t offA = (uint32_t)(lane & 15) * (RS*4) + (uint32_t)((lane >> 4) & 1) * 16;
    uint32_t offB = (uint32_t)((lane & 7) + ((lane >> 4) & 1) * 8) * (RS*4)
                  + (uint32_t)((lane >> 3) & 1) * 16;

    float acc[4][4][4];
    #pragma unroll
    for (int i = 0; i < 4; i++)
        #pragma unroll
        for (int j = 0; j < 4; j++)
            #pragma unroll
            for (int e = 0; e < 4; e++) acc[i][j][e] = 0.f;

    uint4 rA0, rA1, rB0, rB1;
    #define GLOAD(c) do { \
        size_t o0_ = (size_t)lr*CDP + (size_t)(c)*8 + kp; \
        size_t o1_ = (size_t)(lr+64)*CDP + (size_t)(c)*8 + kp; \
        rA0 = *(const uint4*)(Ag + o0_); rA1 = *(const uint4*)(Ag + o1_); \
        rB0 = *(const uint4*)(Bg + o0_); rB1 = *(const uint4*)(Bg + o1_); \
    } while (0)
    #define GSTAGE(bi) do { \
        *(uint2*)&Ah[bi][lr][kp]    = make_uint2(rA0.x, rA0.z); \
        *(uint2*)&Al[bi][lr][kp]    = make_uint2(rA0.y, rA0.w); \
        *(uint2*)&Ah[bi][lr+64][kp] = make_uint2(rA1.x, rA1.z); \
        *(uint2*)&Al[bi][lr+64][kp] = make_uint2(rA1.y, rA1.w); \
        *(uint2*)&Bh[bi][lr][kp]    = make_uint2(rB0.x, rB0.z); \
        *(uint2*)&Bl[bi][lr][kp]    = make_uint2(rB0.y, rB0.w); \
        *(uint2*)&Bh[bi][lr+64][kp] = make_uint2(rB1.x, rB1.z); \
        *(uint2*)&Bl[bi][lr+64][kp] = make_uint2(rB1.y, rB1.w); \
    } while (0)

    const int NC = CD / 16;    // 32
    GLOAD(0); GSTAGE(0); GLOAD(1);
    __syncthreads();

    for (int c = 0; c < NC; c++) {
        uint32_t cb = (uint32_t)(c & 1) * BUF;
        uint32_t bh[4][2], bl[4][2];
        #pragma unroll
        for (int ntp = 0; ntp < 2; ntp++) {
            uint32_t nbase = (uint32_t)(wn*32 + ntp*16) * (RS*4);
            ldsm4(bh[2*ntp][0], bh[2*ntp][1], bh[2*ntp+1][0], bh[2*ntp+1][1], aBh + cb + nbase + offB);
            ldsm4(bl[2*ntp][0], bl[2*ntp][1], bl[2*ntp+1][0], bl[2*ntp+1][1], aBl + cb + nbase + offB);
        }
        #pragma unroll
        for (int mt = 0; mt < 4; mt++) {
            uint32_t rbase = (uint32_t)(wm*64 + mt*16) * (RS*4);
            uint32_t ah0, ah1, ah2, ah3, al0, al1, al2, al3;
            ldsm4(ah0, ah1, ah2, ah3, aAh + cb + rbase + offA);
            ldsm4(al0, al1, al2, al3, aAl + cb + rbase + offA);
            #pragma unroll
            for (int nt = 0; nt < 4; nt++) {
                mma16(acc[mt][nt][0], acc[mt][nt][1], acc[mt][nt][2], acc[mt][nt][3],
                      ah0, ah1, ah2, ah3, bh[nt][0], bh[nt][1]);
                mma16(acc[mt][nt][0], acc[mt][nt][1], acc[mt][nt][2], acc[mt][nt][3],
                      ah0, ah1, ah2, ah3, bl[nt][0], bl[nt][1]);
                mma16(acc[mt][nt][0], acc[mt][nt][1], acc[mt][nt][2], acc[mt][nt][3],
                      al0, al1, al2, al3, bh[nt][0], bh[nt][1]);
            }
        }
        if (c + 1 < NC) {
            GSTAGE((c+1) & 1);
            if (c + 2 < NC) GLOAD(c+2);
        }
        __syncthreads();
    }
    #undef GLOAD
    #undef GSTAGE

    if (mode <= 1) {
        uint2* O = (mode == 0) ? g_qp : g_kp;
        #pragma unroll
        for (int mt = 0; mt < 4; mt++) {
            int r = m0 + wm*64 + mt*16 + qr;
            #pragma unroll
            for (int nt = 0; nt < 4; nt++) {
                int colp = (n0 >> 1) + wn*16 + nt*4 + qc;
                uint2 pk;
                split2(acc[mt][nt][0]*scale, acc[mt][nt][1]*scale, pk.x, pk.y);
                O[(size_t)r*CDP + colp] = pk;
                split2(acc[mt][nt][2]*scale, acc[mt][nt][3]*scale, pk.x, pk.y);
                O[(size_t)(r+8)*CDP + colp] = pk;
            }
        }
    } else {
        float* O = (mode == 2) ? g_v : g_gate;
        #pragma unroll
        for (int mt = 0; mt < 4; mt++) {
            int r = m0 + wm*64 + mt*16 + qr;
            #pragma unroll
            for (int nt = 0; nt < 4; nt++) {
                int col = n0 + wn*32 + nt*8 + qc*2;
                float o0 = acc[mt][nt][0], o1 = acc[mt][nt][1];
                float o2 = acc[mt][nt][2], o3 = acc[mt][nt][3];
                if (mode == 3) {
                    float b0 = bg[col], b1 = bg[col+1];
                    o0 = 1.0f/(1.0f + __expf(-(o0+b0)));
                    o1 = 1.0f/(1.0f + __expf(-(o1+b1)));
                    o2 = 1.0f/(1.0f + __expf(-(o2+b0)));
                    o3 = 1.0f/(1.0f + __expf(-(o3+b1)));
                }
                *(float2*)(O + (size_t)r*CD + col)     = make_float2(o0, o1);
                *(float2*)(O + (size_t)(r+8)*CD + col) = make_float2(o2, o3);
            }
        }
    }
}

// ---------------- scores + stats: smem-staged coalesced P stores ------------
#define PTS 68   // P-tile row stride in uint32 (16B-aligned, conflict-free)
__global__ __launch_bounds__(256, 2)
void scores_stats()
{
    __shared__ uint32_t SM[8*128*RS];   // 48KB: staging during mainloop, P-tile after
    uint32_t aAh = s2u(SM);
    uint32_t aAl = aAh + 2*128*RS*4;
    uint32_t aBh = aAh + 4*128*RS*4;
    uint32_t aBl = aAh + 6*128*RS*4;
    int z = blockIdx.z, b = z >> 3, h = z & 7;
    int m0 = blockIdx.y * 128, n0 = blockIdx.x * 128;
    int tid = threadIdx.x, wid = tid >> 5, lane = tid & 31;
    int wm = wid & 1, wn = wid >> 1;
    int lr = tid >> 2, kp = (tid & 3) * 2;
    int qr = lane >> 2, qc = lane & 3;

    const uint2* Ag = g_qp + (size_t)(b*CS + m0)*CDP + h*32;
    const uint2* Bg = g_kp + (size_t)(b*CS + n0)*CDP + h*32;

    const uint32_t BUF = 128*RS*4;
    uint32_t offA = (uint32_t)(lane & 15) * (RS*4) + (uint32_t)((lane >> 4) & 1) * 16;
    uint32_t offB = (uint32_t)((lane & 7) + ((lane >> 4) & 1) * 8) * (RS*4)
                  + (uint32_t)((lane >> 3) & 1) * 16;

    float acc[4][4][4];
    #pragma unroll
    for (int i = 0; i < 4; i++)
        #pragma unroll
        for (int j = 0; j < 4; j++)
            #pragma unroll
            for (int e = 0; e < 4; e++) acc[i][j][e] = 0.f;

    uint4 rA0, rA1, rB0, rB1;
    #define SSTORE(addr, v2_) asm volatile("st.shared.v2.u32 [%0], {%1,%2};" \
        :: "r"(addr), "r"((v2_).x), "r"((v2_).y) : "memory")
    #define SLOAD(c) do { \
        size_t o0_ = (size_t)lr*CDP + (size_t)(c)*8 + kp; \
        size_t o1_ = (size_t)(lr+64)*CDP + (size_t)(c)*8 + kp; \
        rA0 = *(const uint4*)(Ag + o0_); rA1 = *(const uint4*)(Ag + o1_); \
        rB0 = *(const uint4*)(Bg + o0_); rB1 = *(const uint4*)(Bg + o1_); \
    } while (0)
    #define SSTAGE(bi) do { \
        uint32_t rowb = (uint32_t)lr*(RS*4) + (uint32_t)kp*4 + (bi)*BUF; \
        uint32_t rowb2 = rowb + 64*(RS*4); \
        SSTORE(aAh + rowb,  make_uint2(rA0.x, rA0.z)); \
        SSTORE(aAl + rowb,  make_uint2(rA0.y, rA0.w)); \
        SSTORE(aAh + rowb2, make_uint2(rA1.x, rA1.z)); \
        SSTORE(aAl + rowb2, make_uint2(rA1.y, rA1.w)); \
        SSTORE(aBh + rowb,  make_uint2(rB0.x, rB0.z)); \
        SSTORE(aBl + rowb,  make_uint2(rB0.y, rB0.w)); \
        SSTORE(aBh + rowb2, make_uint2(rB1.x, rB1.z)); \
        SSTORE(aBl + rowb2, make_uint2(rB1.y, rB1.w)); \
    } while (0)

    const int NC = CDK / 16;   // 4
    SLOAD(0); SSTAGE(0); SLOAD(1);
    __syncthreads();

    for (int c = 0; c < NC; c++) {
        uint32_t cb = (uint32_t)(c & 1) * BUF;
        uint32_t bh[4][2], bl[4][2];
        #pragma unroll
        for (int ntp = 0; ntp < 2; ntp++) {
            uint32_t nbase = (uint32_t)(wn*32 + ntp*16) * (RS*4);
            ldsm4(bh[2*ntp][0], bh[2*ntp][1], bh[2*ntp+1][0], bh[2*ntp+1][1], aBh + cb + nbase + offB);
            ldsm4(bl[2*ntp][0], bl[2*ntp][1], bl[2*ntp+1][0], bl[2*ntp+1][1], aBl + cb + nbase + offB);
        }
        #pragma unroll
        for (int mt = 0; mt < 4; mt++) {
            uint32_t rbase = (uint32_t)(wm*64 + mt*16) * (RS*4);
            uint32_t ah0, ah1, ah2, ah3, al0, al1, al2, al3;
            ldsm4(ah0, ah1, ah2, ah3, aAh + cb + rbase + offA);
            ldsm4(al0, al1, al2, al3, aAl + cb + rbase + offA);
            #pragma unroll
            for (int nt = 0; nt < 4; nt++) {
                mma16(acc[mt][nt][0], acc[mt][nt][1], acc[mt][nt][2], acc[mt][nt][3],
                      ah0, ah1, ah2, ah3, bh[nt][0], bh[nt][1]);
                mma16(acc[mt][nt][0], acc[mt][nt][1], acc[mt][nt][2], acc[mt][nt][3],
                      ah0, ah1, ah2, ah3, bl[nt][0], bl[nt][1]);
                mma16(acc[mt][nt][0], acc[mt][nt][1], acc[mt][nt][2], acc[mt][nt][3],
                      al0, al1, al2, al3, bh[nt][0], bh[nt][1]);
            }
        }
        if (c + 1 < NC) {
            SSTAGE((c+1) & 1);
            if (c + 2 < NC) SLOAD(c+2);
        }
        __syncthreads();
    }
    #undef SLOAD
    #undef SSTAGE
    #undef SSTORE

    // epilogue: ex = exp(x); stats; P fragments -> SMEM tile (streamed STS),
    // then coalesced uint4 global stores. SM is dead post-mainloop.
    uint32_t* Pt = SM;   // [128][PTS]
    float csl[4][2];
    #pragma unroll
    for (int nt = 0; nt < 4; nt++) { csl[nt][0] = 0.f; csl[nt][1] = 0.f; }
    #pragma unroll
    for (int mt = 0; mt < 4; mt++) {
        float ex[4][4];
        #pragma unroll
        for (int nt = 0; nt < 4; nt++)
            #pragma unroll
            for (int e = 0; e < 4; e++) ex[nt][e] = fast_exp(acc[mt][nt][e]);
        float r0 = 0.f, r1 = 0.f;
        #pragma unroll
        for (int nt = 0; nt < 4; nt++) {
            r0 += ex[nt][0] + ex[nt][1];
            r1 += ex[nt][2] + ex[nt][3];
            csl[nt][0] += ex[nt][0] + ex[nt][2];
            csl[nt][1] += ex[nt][1] + ex[nt][3];
        }
        r0 += __shfl_xor_sync(0xffffffffu, r0, 1);
        r0 += __shfl_xor_sync(0xffffffffu, r0, 2);
        r1 += __shfl_xor_sync(0xffffffffu, r1, 1);
        r1 += __shfl_xor_sync(0xffffffffu, r1, 2);
        int lrow0 = wm*64 + mt*16 + qr;
        if (qc == 0) {
            int rslot = blockIdx.x * 4 + wn;
            g_rpart[((size_t)(z*CS + m0 + lrow0) << 6) + rslot]     = r0;
            g_rpart[((size_t)(z*CS + m0 + lrow0 + 8) << 6) + rslot] = r1;
        }
        #pragma unroll
        for (int nt = 0; nt < 4; nt++) {
            int pc_ = wn*16 + nt*4 + qc;
            Pt[lrow0*PTS + pc_]       = pack_h2(ex[nt][0]*ex[nt][0]*PSCALE,
                                                ex[nt][1]*ex[nt][1]*PSCALE);
            Pt[(lrow0 + 8)*PTS + pc_] = pack_h2(ex[nt][2]*ex[nt][2]*PSCALE,
                                                ex[nt][3]*ex[nt][3]*PSCALE);
        }
    }
    #pragma unroll
    for (int nt = 0; nt < 4; nt++) {
        #pragma unroll
        for (int j = 0; j < 2; j++) {
            float v = csl[nt][j];
            v += __shfl_xor_sync(0xffffffffu, v, 4);
            v += __shfl_xor_sync(0xffffffffu, v, 8);
            v += __shfl_xor_sync(0xffffffffu, v, 16);
            if (qr == 0) {
                int cslot = blockIdx.y * 2 + wm;
                int col = n0 + wn*32 + nt*8 + qc*2 + j;
                g_cpart[((size_t)(z*CS + col) << 5) + cslot] = v;
            }
        }
    }
    __syncthreads();
    // coalesced store: 128 rows x 16 uint4
    #pragma unroll
    for (int i = 0; i < 8; i++) {
        int idx = tid + i*256;
        int row = idx >> 4, c4 = (idx & 15) * 4;
        uint4 v = *(uint4*)&Pt[row*PTS + c4];
        *(uint4*)(g_p + (size_t)(z*CS + m0 + row)*CSP + (n0 >> 1) + c4) = v;
    }
}

// ---------------- finalize: reduce partials -> reciprocals ------------------
__global__ __launch_bounds__(256)
void finalize_kernel()
{
    int i = blockIdx.x * 256 + threadIdx.x;
    if (i < CBH*CS) {
        const float4* p = (const float4*)(g_rpart + ((size_t)i << 6));
        float s = 0.f;
        #pragma unroll
        for (int j = 0; j < 16; j++) {
            float4 v = p[j];
            s += v.x + v.y + v.z + v.w;
        }
        g_rsum[i] = 1.0f / s;
    } else {
        i -= CBH*CS;
        const float4* p = (const float4*)(g_cpart + ((size_t)i << 5));
        float s = 0.f;
        #pragma unroll
        for (int j = 0; j < 8; j++) {
            float4 v = p[j];
            s += v.x + v.y + v.z + v.w;
        }
        g_csum[i] = 1.0f / s;
    }
}

// ---------------- V transpose: ci*256 folded, fp16 split packed -------------
__global__ __launch_bounds__(256)
void vtrans_ci()
{
    __shared__ float tile[64][65];
    int z = blockIdx.y, b = z >> 3, h = z & 7;
    int t0 = blockIdx.x * 64;
    const float* src = g_v + (size_t)b*CS*CD + h*CDK;
    int tid = threadIdx.x;
    #pragma unroll
    for (int i = 0; i < 16; i++) {
        int idx = tid + i*256;
        int tr = idx >> 6, d = idx & 63;
        tile[tr][d] = src[(size_t)(t0 + tr)*CD + d] * (g_csum[z*CS + t0 + tr] * VSCALE);
    }
    __syncthreads();
    #pragma unroll
    for (int i = 0; i < 8; i++) {
        int idx = tid + i*256;
        int d = idx >> 5, tp = idx & 31;
        uint2 pk;
        splith2(tile[2*tp][d], tile[2*tp+1][d], pk.x, pk.y);
        g_vtp[((size_t)z*CDK + d)*CSP + (t0 >> 1) + tp] = pk;
    }
}

// ---------------- PV: fp16 P (single) x fp16 V (split), packed out ----------
__global__ __launch_bounds__(256)
void pv_kernel()
{
    __shared__ uint32_t Ph[2][128][RS];
    __shared__ uint32_t Vh[2][64][RS], Vl[2][64][RS];
    int z = blockIdx.y, b = z >> 3, h = z & 7;
    int s0 = blockIdx.x * 128;
    int tid = threadIdx.x, wid = tid >> 5, lane = tid & 31;
    int wm = wid & 3, wn = wid >> 2;
    int qr = lane >> 2, qc = lane & 3;

    int pr = tid >> 1;                 // P row 0..127
    int pp = (tid & 1) * 4;            // uint32 base 0/4 within 8-u32 chunk row
    int vr = tid >> 2;                 // V^T row (dk) 0..63
    int vp = (tid & 3) * 2;            // pair base 0,2,4,6
    const uint32_t* aph = g_p   + (size_t)(z*CS + s0 + pr)*CSP;
    const uint2*    avh = g_vtp + ((size_t)z*CDK + vr)*CSP;

    const uint32_t BUFP = 128*RS*4, BUFV = 64*RS*4;
    uint32_t aPh = s2u(Ph), aVh = s2u(Vh), aVl = s2u(Vl);
    uint32_t offA = (uint32_t)(lane & 15) * (RS*4) + (uint32_t)((lane >> 4) & 1) * 16;
    uint32_t offB = (uint32_t)((lane & 7) + ((lane >> 4) & 1) * 8) * (RS*4)
                  + (uint32_t)((lane >> 3) & 1) * 16;

    float acc[2][4][4];
    #pragma unroll
    for (int i = 0; i < 2; i++)
        #pragma unroll
        for (int j = 0; j < 4; j++)
            #pragma unroll
            for (int e = 0; e < 4; e++) acc[i][j][e] = 0.f;

    uint4 rp0, rv0;
    #define PLOAD(c) do { \
        rp0 = *(const uint4*)(aph + (size_t)(c)*8 + pp); \
        rv0 = *(const uint4*)(avh + (size_t)(c)*8 + vp); \
    } while (0)
    #define PSTAGE(bi) do { \
        *(uint4*)&Ph[bi][pr][pp] = rp0; \
        *(uint2*)&Vh[bi][vr][vp] = make_uint2(rv0.x, rv0.z); \
        *(uint2*)&Vl[bi][vr][vp] = make_uint2(rv0.y, rv0.w); \
    } while (0)

    const int NC = CS / 16;            // 128 chunks
    PLOAD(0); PSTAGE(0); PLOAD(1);
    __syncthreads();

    for (int c = 0; c < NC; c++) {
        uint32_t cbP = (uint32_t)(c & 1) * BUFP;
        uint32_t cbV = (uint32_t)(c & 1) * BUFV;
        uint32_t bh[4][2], bl[4][2];
        #pragma unroll
        for (int ntp = 0; ntp < 2; ntp++) {
            uint32_t nbase = (uint32_t)(wn*32 + ntp*16) * (RS*4);
            ldsm4(bh[2*ntp][0], bh[2*ntp][1], bh[2*ntp+1][0], bh[2*ntp+1][1], aVh + cbV + nbase + offB);
            ldsm4(bl[2*ntp][0], bl[2*ntp][1], bl[2*ntp+1][0], bl[2*ntp+1][1], aVl + cbV + nbase + offB);
        }
        #pragma unroll
        for (int mt = 0; mt < 2; mt++) {
            uint32_t rbase = (uint32_t)(wm*32 + mt*16) * (RS*4);
            uint32_t a0, a1, a2, a3;
            ldsm4(a0, a1, a2, a3, aPh + cbP + rbase + offA);
            #pragma unroll
            for (int nt = 0; nt < 4; nt++) {
                mma16h(acc[mt][nt][0], acc[mt][nt][1], acc[mt][nt][2], acc[mt][nt][3],
                       a0, a1, a2, a3, bh[nt][0], bh[nt][1]);
                mma16h(acc[mt][nt][0], acc[mt][nt][1], acc[mt][nt][2], acc[mt][nt][3],
                       a0, a1, a2, a3, bl[nt][0], bl[nt][1]);
            }
        }
        if (c + 1 < NC) {
            PSTAGE((c+1) & 1);
            if (c + 2 < NC) PLOAD(c+2);
        }
        __syncthreads();
    }
    #undef PLOAD
    #undef PSTAGE
    // epilogue: * rsum_inv, * gate -> g_aop (packed bf16 split)
    #pragma unroll
    for (int mt = 0; mt < 2; mt++) {
        #pragma unroll
        for (int half = 0; half < 2; half++) {
            int srow = s0 + wm*32 + mt*16 + qr + half*8;
            float ri = g_rsum[(size_t)z*CS + srow];
            const float* grow = g_gate + ((size_t)b*CS + srow)*CD + h*CDK;
            uint2* orow       = g_aop  + ((size_t)b*CS + srow)*CDP + h*32;
            #pragma unroll
            for (int nt = 0; nt < 4; nt++) {
                int col = wn*32 + nt*8 + qc*2;
                float2 gg = *(const float2*)(grow + col);
                float o0 = acc[mt][nt][half*2+0] * ri * gg.x;
                float o1 = acc[mt][nt][half*2+1] * ri * gg.y;
                uint2 pk;
                split2(o0, o1, pk.x, pk.y);
                orow[col >> 1] = pk;
            }
        }
    }
}

// ---------------- output projection: packed A/B, bias -> d_out --------------
__global__ __launch_bounds__(256, 2)
void out_gemm(const float* __restrict__ bo, float* __restrict__ C)
{
    __shared__ uint32_t Ah[2][128][RS], Al[2][128][RS];
    __shared__ uint32_t Bh[2][128][RS], Bl[2][128][RS];
    int tid = threadIdx.x, wid = tid >> 5, lane = tid & 31;
    int wm = wid & 1, wn = wid >> 1;
    int m0 = blockIdx.y * 128, n0 = blockIdx.x * 128;
    const uint2* Ag = g_aop + (size_t)m0 * CDP;
    const uint2* Bg = g_wp[4] + (size_t)n0 * CDP;
    int lr = tid >> 2, kp = (tid & 3) * 2;
    int qr = lane >> 2, qc = lane & 3;

    const uint32_t BUF = 128*RS*4;
    uint32_t aAh = s2u(Ah), aAl = s2u(Al), aBh = s2u(Bh), aBl = s2u(Bl);
    uint32_t offA = (uint32_t)(lane & 15) * (RS*4) + (uint32_t)((lane >> 4) & 1) * 16;
    uint32_t offB = (uint32_t)((lane & 7) + ((lane >> 4) & 1) * 8) * (RS*4)
                  + (uint32_t)((lane >> 3) & 1) * 16;

    float acc[4][4][4];
    #pragma unroll
    for (int i = 0; i < 4; i++)
        #pragma unroll
        for (int j = 0; j < 4; j++)
            #pragma unroll
            for (int e = 0; e < 4; e++) acc[i][j][e] = 0.f;

    uint4 rA0, rA1, rB0, rB1;
    #define OLOAD(c) do { \
        size_t o0_ = (size_t)lr*CDP + (size_t)(c)*8 + kp; \
        size_t o1_ = (size_t)(lr+64)*CDP + (size_t)(c)*8 + kp; \
        rA0 = *(const uint4*)(Ag + o0_); rA1 = *(const uint4*)(Ag + o1_); \
        rB0 = *(const uint4*)(Bg + o0_); rB1 = *(const uint4*)(Bg + o1_); \
    } while (0)
    #define OSTAGE(bi) do { \
        *(uint2*)&Ah[bi][lr][kp]    = make_uint2(rA0.x, rA0.z); \
        *(uint2*)&Al[bi][lr][kp]    = make_uint2(rA0.y, rA0.w); \
        *(uint2*)&Ah[bi][lr+64][kp] = make_uint2(rA1.x, rA1.z); \
        *(uint2*)&Al[bi][lr+64][kp] = make_uint2(rA1.y, rA1.w); \
        *(uint2*)&Bh[bi][lr][kp]    = make_uint2(rB0.x, rB0.z); \
        *(uint2*)&Bl[bi][lr][kp]    = make_uint2(rB0.y, rB0.w); \
        *(uint2*)&Bh[bi][lr+64][kp] = make_uint2(rB1.x, rB1.z); \
        *(uint2*)&Bl[bi][lr+64][kp] = make_uint2(rB1.y, rB1.w); \
    } while (0)

    const int NC = CD / 16;
    OLOAD(0); OSTAGE(0); OLOAD(1);
    __syncthreads();

    for (int c = 0; c < NC; c++) {
        uint32_t cb = (uint32_t)(c & 1) * BUF;
        uint32_t bh[4][2], bl[4][2];
        #pragma unroll
        for (int ntp = 0; ntp < 2; ntp++) {
            uint32_t nbase = (uint32_t)(wn*32 + ntp*16) * (RS*4);
            ldsm4(bh[2*ntp][0], bh[2*ntp][1], bh[2*ntp+1][0], bh[2*ntp+1][1], aBh + cb + nbase + offB);
            ldsm4(bl[2*ntp][0], bl[2*ntp][1], bl[2*ntp+1][0], bl[2*ntp+1][1], aBl + cb + nbase + offB);
        }
        #pragma unroll
        for (int mt = 0; mt < 4; mt++) {
            uint32_t rbase = (uint32_t)(wm*64 + mt*16) * (RS*4);
            uint32_t ah0, ah1, ah2, ah3, al0, al1, al2, al3;
            ldsm4(ah0, ah1, ah2, ah3, aAh + cb + rbase + offA);
            ldsm4(al0, al1, al2, al3, aAl + cb + rbase + offA);
            #pragma unroll
            for (int nt = 0; nt < 4; nt++) {
                mma16(acc[mt][nt][0], acc[mt][nt][1], acc[mt][nt][2], acc[mt][nt][3],
                      ah0, ah1, ah2, ah3, bh[nt][0], bh[nt][1]);
                mma16(acc[mt][nt][0], acc[mt][nt][1], acc[mt][nt][2], acc[mt][nt][3],
                      ah0, ah1, ah2, ah3, bl[nt][0], bl[nt][1]);
                mma16(acc[mt][nt][0], acc[mt][nt][1], acc[mt][nt][2], acc[mt][nt][3],
                      al0, al1, al2, al3, bh[nt][0], bh[nt][1]);
            }
        }
        if (c + 1 < NC) {
            OSTAGE((c+1) & 1);
            if (c + 2 < NC) OLOAD(c+2);
        }
        __syncthreads();
    }
    #undef OLOAD
    #undef OSTAGE
    #pragma unroll
    for (int mt = 0; mt < 4; mt++) {
        int r = m0 + wm*64 + mt*16 + qr;
        #pragma unroll
        for (int nt = 0; nt < 4; nt++) {
            int col = n0 + wn*32 + nt*8 + qc*2;
            float b0 = bo[col], b1 = bo[col+1];
            *(float2*)(C + (size_t)r*CD + col) =
                make_float2(acc[mt][nt][0] + b0, acc[mt][nt][1] + b1);
            *(float2*)(C + (size_t)(r+8)*CD + col) =
                make_float2(acc[mt][nt][2] + b0, acc[mt][nt][3] + b1);
        }
    }
}

// ---------------- launch ----------------
extern "C" void kernel_launch(void* const* d_in, const int* in_sizes, int n_in,
                              void* d_out, int out_size)
{
    const float* x_q   = (const float*)d_in[0];
    const float* x_k   = (const float*)d_in[1];
    const float* Wq    = (const float*)d_in[2];
    const float* Wk    = (const float*)d_in[3];
    const float* Wv    = (const float*)d_in[4];
    const float* Wg    = (const float*)d_in[5];
    const float* bg    = (const float*)d_in[6];
    const float* Wo    = (const float*)d_in[7];
    const float* bo    = (const float*)d_in[8];
    const float* gamma = (const float*)d_in[9];
    const float* beta  = (const float*)d_in[10];
    float* out = (float*)d_out;

    // 1. LayerNorm (packed-split output) + weight split
    ln_kernel<<<2*CM, 256>>>(x_q, x_k, gamma, beta);
    wsplit_kernel<<<dim3(CD*CDP/256, 5), 256>>>(Wq, Wk, Wv, Wg, Wo);

    // 2. All projections, one launch (copy-staged)
    proj_all<<<dim3(CD/128, CM/128, 4), 256>>>(bg);

    // 3. Scores + stats, fp16 exp(2x)*2^-8, smem-staged coalesced stores
    scores_stats<<<dim3(CS/128, CS/128, CBH), 256>>>();

    // 4. Reduce partials -> reciprocal sums
    finalize_kernel<<<(2*CBH*CS)/256, 256>>>();

    // 5. V transpose with ci*256 folded, fp16 split
    vtrans_ci<<<dim3(CS/64, CBH), 256>>>();

    // 6. PV: fp16 MMA (2 per tile), packed bf16 split out
    pv_kernel<<<dim3(CS/128, CBH), 256>>>();

    // 7. Output projection (copy-staged) + bias -> d_out
    out_gemm<<<dim3(CD/128, CM/128), 256>>>(bo, out);
}

// round 15
// speedup vs baseline: 1.5534x; 1.0828x over previous
#include <cuda_runtime.h>
#include <cuda_bf16.h>
#include <cuda_fp16.h>
#include <cstdint>
#include <math.h>

#define CB 4
#define CS 2048
#define CD 512
#define CH 8
#define CDK 64
#define CM (CB*CS)      // 8192
#define CBH (CB*CH)     // 32
#define CDP (CD/2)      // 256 pairs per D row
#define CSP (CS/2)      // 1024 pairs per score row

// P stored as exp(2x) * 2^-8 (fp16); V stored as v * ci * 2^8 (single fp16).
#define PSCALE (1.0f/256.0f)
#define VSCALE 256.0f

// ---------------- scratch (device globals: allocation-free) ----------------
static __device__ uint2 g_xqp[CM*CDP];                // LN(xq) packed bf16 split
static __device__ uint2 g_xkp[CM*CDP];                // LN(xk) packed bf16 split
static __device__ uint2 g_wp[5][CD*CDP];              // W: 0-3 bf16 split, 4 fp16 split
static __device__ uint2 g_qp[CM*CDP];                 // q/8 packed bf16 split
static __device__ uint2 g_kp[CM*CDP];                 // k packed bf16 split
static __device__ float g_v[CM*CD];
static __device__ float g_gate[CM*CD];
static __device__ uint32_t g_aop1[CM*CDP];            // attn-out*ri*gate, single fp16 pairs
static __device__ uint32_t g_p[(size_t)CBH*CS*CSP];   // fp16x2: exp(2x)*2^-8
static __device__ uint32_t g_vt1[CBH*CDK*CSP];        // fp16x2: V^T*ci*2^8
static __device__ float g_rpart[(size_t)CBH*CS*64];
static __device__ float g_cpart[(size_t)CBH*CS*32];
static __device__ float g_rsum[CBH*CS];
static __device__ float g_csum[CBH*CS];

// ---------------- helpers ----------------
__device__ __forceinline__ uint32_t s2u(const void* p) {
    return (uint32_t)__cvta_generic_to_shared(p);
}
__device__ __forceinline__ void split2(float x0, float x1, uint32_t &hi, uint32_t &lo) {
    __nv_bfloat16 h0 = __float2bfloat16_rn(x0);
    __nv_bfloat16 h1 = __float2bfloat16_rn(x1);
    float r0 = x0 - __bfloat162float(h0);
    float r1 = x1 - __bfloat162float(h1);
    __nv_bfloat16 l0 = __float2bfloat16_rn(r0);
    __nv_bfloat16 l1 = __float2bfloat16_rn(r1);
    hi = (uint32_t)__bfloat16_as_ushort(h0) | ((uint32_t)__bfloat16_as_ushort(h1) << 16);
    lo = (uint32_t)__bfloat16_as_ushort(l0) | ((uint32_t)__bfloat16_as_ushort(l1) << 16);
}
__device__ __forceinline__ uint32_t pack_h2(float x0, float x1) {
    __half2 h = __floats2half2_rn(x0, x1);
    return *(uint32_t*)&h;
}
__device__ __forceinline__ void splith2(float x0, float x1, uint32_t &hi, uint32_t &lo) {
    __half h0 = __float2half_rn(x0);
    __half h1 = __float2half_rn(x1);
    float r0 = x0 - __half2float(h0);
    float r1 = x1 - __half2float(h1);
    __half l0 = __float2half_rn(r0);
    __half l1 = __float2half_rn(r1);
    hi = (uint32_t)__half_as_ushort(h0) | ((uint32_t)__half_as_ushort(h1) << 16);
    lo = (uint32_t)__half_as_ushort(l0) | ((uint32_t)__half_as_ushort(l1) << 16);
}
__device__ __forceinline__ void mma16(float &c0, float &c1, float &c2, float &c3,
                                      uint32_t a0, uint32_t a1, uint32_t a2, uint32_t a3,
                                      uint32_t b0, uint32_t b1) {
    asm("mma.sync.aligned.m16n8k16.row.col.f32.bf16.bf16.f32 "
        "{%0,%1,%2,%3}, {%4,%5,%6,%7}, {%8,%9}, {%0,%1,%2,%3};"
        : "+f"(c0), "+f"(c1), "+f"(c2), "+f"(c3)
        : "r"(a0), "r"(a1), "r"(a2), "r"(a3), "r"(b0), "r"(b1));
}
__device__ __forceinline__ void mma16h(float &c0, float &c1, float &c2, float &c3,
                                       uint32_t a0, uint32_t a1, uint32_t a2, uint32_t a3,
                                       uint32_t b0, uint32_t b1) {
    asm("mma.sync.aligned.m16n8k16.row.col.f32.f16.f16.f32 "
        "{%0,%1,%2,%3}, {%4,%5,%6,%7}, {%8,%9}, {%0,%1,%2,%3};"
        : "+f"(c0), "+f"(c1), "+f"(c2), "+f"(c3)
        : "r"(a0), "r"(a1), "r"(a2), "r"(a3), "r"(b0), "r"(b1));
}
__device__ __forceinline__ void ldsm4(uint32_t &r0, uint32_t &r1, uint32_t &r2, uint32_t &r3,
                                      uint32_t addr) {
    asm volatile("ldmatrix.sync.aligned.m8n8.x4.shared.b16 {%0,%1,%2,%3}, [%4];"
                 : "=r"(r0), "=r"(r1), "=r"(r2), "=r"(r3) : "r"(addr));
}
#define RS 12   // SMEM row stride in uint32 (48B, conflict-free)

__device__ __forceinline__ float fast_exp(float x) {
    x = fmaxf(x, -80.0f);
    float t  = x * 1.4426950408889634f;
    float fi = floorf(t);
    float f  = t - fi;
    float p  = 1.53533e-4f;
    p = fmaf(p, f, 1.33989e-3f);
    p = fmaf(p, f, 9.61844e-3f);
    p = fmaf(p, f, 5.55033e-2f);
    p = fmaf(p, f, 2.40226e-1f);
    p = fmaf(p, f, 6.93147e-1f);
    p = fmaf(p, f, 1.0f);
    return __int_as_float(((int)fi + 127) << 23) * p;
}

// ---------------- LayerNorm -> packed split ----------------
__global__ __launch_bounds__(256)
void ln_kernel(const float* __restrict__ xq, const float* __restrict__ xk,
               const float* __restrict__ gamma, const float* __restrict__ beta)
{
    int row = blockIdx.x;
    const float* x; uint2* o;
    if (row < CM) { x = xq + (size_t)row*CD;       o = g_xqp + (size_t)row*CDP; }
    else          { x = xk + (size_t)(row-CM)*CD;  o = g_xkp + (size_t)(row-CM)*CDP; }
    int t = threadIdx.x;
    float2 v2 = ((const float2*)x)[t];
    float s  = v2.x + v2.y;
    float ss = v2.x*v2.x + v2.y*v2.y;
    #pragma unroll
    for (int off = 16; off; off >>= 1) {
        s  += __shfl_xor_sync(0xffffffffu, s,  off);
        ss += __shfl_xor_sync(0xffffffffu, ss, off);
    }
    __shared__ float sh_s[8], sh_ss[8];
    __shared__ float s_mean, s_rstd;
    int wid = t >> 5, lid = t & 31;
    if (lid == 0) { sh_s[wid] = s; sh_ss[wid] = ss; }
    __syncthreads();
    if (t < 32) {
        float a = (t < 8) ? sh_s[t]  : 0.f;
        float b = (t < 8) ? sh_ss[t] : 0.f;
        #pragma unroll
        for (int off = 4; off; off >>= 1) {
            a += __shfl_xor_sync(0xffffffffu, a, off);
            b += __shfl_xor_sync(0xffffffffu, b, off);
        }
        if (t == 0) {
            float mean = a * (1.0f/CD);
            float var  = b * (1.0f/CD) - mean*mean;
            s_mean = mean;
            s_rstd = rsqrtf(var + 1e-6f);
        }
    }
    __syncthreads();
    float mean = s_mean, rstd = s_rstd;
    float2 g2 = ((const float2*)gamma)[t];
    float2 b2 = ((const float2*)beta)[t];
    float o0 = (v2.x - mean) * rstd * g2.x + b2.x;
    float o1 = (v2.y - mean) * rstd * g2.y + b2.y;
    uint2 pk;
    split2(o0, o1, pk.x, pk.y);
    o[t] = pk;
}

// ---------------- weight split: 0-3 bf16, 4 (Wo) fp16 ----------------------
__global__ __launch_bounds__(256)
void wsplit_kernel(const float* __restrict__ Wq, const float* __restrict__ Wk,
                   const float* __restrict__ Wv, const float* __restrict__ Wg,
                   const float* __restrict__ Wo)
{
    int m = blockIdx.y;
    const float* W = (m == 0) ? Wq : (m == 1) ? Wk : (m == 2) ? Wv : (m == 3) ? Wg : Wo;
    int idx = blockIdx.x * 256 + threadIdx.x;
    float2 v = ((const float2*)W)[idx];
    uint2 pk;
    if (m == 4) splith2(v.x, v.y, pk.x, pk.y);
    else        split2(v.x, v.y, pk.x, pk.y);
    g_wp[m][idx] = pk;
}

// ---------------- merged projections (packed operands, bf16x3) --------------
__global__ __launch_bounds__(256, 2)
void proj_all(const float* __restrict__ bg)
{
    __shared__ uint32_t Ah[2][128][RS], Al[2][128][RS];
    __shared__ uint32_t Bh[2][128][RS], Bl[2][128][RS];
    int mode = blockIdx.z;
    const uint2* A = (mode == 0 || mode == 3) ? g_xqp : g_xkp;
    const uint2* B = g_wp[mode];
    float scale = (mode == 0) ? 0.125f : 1.0f;

    int tid = threadIdx.x, wid = tid >> 5, lane = tid & 31;
    int wm = wid & 1, wn = wid >> 1;
    int m0 = blockIdx.y * 128, n0 = blockIdx.x * 128;
    const uint2* Ag = A + (size_t)m0 * CDP;
    const uint2* Bg = B + (size_t)n0 * CDP;
    int lr = tid >> 2, kp = (tid & 3) * 2;
    int qr = lane >> 2, qc = lane & 3;

    const uint32_t BUF = 128*RS*4;
    uint32_t aAh = s2u(Ah), aAl = s2u(Al), aBh = s2u(Bh), aBl = s2u(Bl);
    uint32_t offA = (uint32_t)(lane & 15) * (RS*4) + (uint32_t)((lane >> 4) & 1) * 16;
    uint32_t offB = (uint32_t)((lane & 7) + ((lane >> 4) & 1) * 8) * (RS*4)
                  + (uint32_t)((lane >> 3) & 1) * 16;

    float acc[4][4][4];
    #pragma unroll
    for (int i = 0; i < 4; i++)
        #pragma unroll
        for (int j = 0; j < 4; j++)
            #pragma unroll
            for (int e = 0; e < 4; e++) acc[i][j][e] = 0.f;

    uint4 rA0, rA1, rB0, rB1;
    #define GLOAD(c) do { \
        size_t o0_ = (size_t)lr*CDP + (size_t)(c)*8 + kp; \
        size_t o1_ = (size_t)(lr+64)*CDP + (size_t)(c)*8 + kp; \
        rA0 = *(const uint4*)(Ag + o0_); rA1 = *(const uint4*)(Ag + o1_); \
        rB0 = *(const uint4*)(Bg + o0_); rB1 = *(const uint4*)(Bg + o1_); \
    } while (0)
    #define GSTAGE(bi) do { \
        *(uint2*)&Ah[bi][lr][kp]    = make_uint2(rA0.x, rA0.z); \
        *(uint2*)&Al[bi][lr][kp]    = make_uint2(rA0.y, rA0.w); \
        *(uint2*)&Ah[bi][lr+64][kp] = make_uint2(rA1.x, rA1.z); \
        *(uint2*)&Al[bi][lr+64][kp] = make_uint2(rA1.y, rA1.w); \
        *(uint2*)&Bh[bi][lr][kp]    = make_uint2(rB0.x, rB0.z); \
        *(uint2*)&Bl[bi][lr][kp]    = make_uint2(rB0.y, rB0.w); \
        *(uint2*)&Bh[bi][lr+64][kp] = make_uint2(rB1.x, rB1.z); \
        *(uint2*)&Bl[bi][lr+64][kp] = make_uint2(rB1.y, rB1.w); \
    } while (0)

    const int NC = CD / 16;    // 32
    GLOAD(0); GSTAGE(0); GLOAD(1);
    __syncthreads();

    for (int c = 0; c < NC; c++) {
        uint32_t cb = (uint32_t)(c & 1) * BUF;
        uint32_t bh[4][2], bl[4][2];
        #pragma unroll
        for (int ntp = 0; ntp < 2; ntp++) {
            uint32_t nbase = (uint32_t)(wn*32 + ntp*16) * (RS*4);
            ldsm4(bh[2*ntp][0], bh[2*ntp][1], bh[2*ntp+1][0], bh[2*ntp+1][1], aBh + cb + nbase + offB);
            ldsm4(bl[2*ntp][0], bl[2*ntp][1], bl[2*ntp+1][0], bl[2*ntp+1][1], aBl + cb + nbase + offB);
        }
        #pragma unroll
        for (int mt = 0; mt < 4; mt++) {
            uint32_t rbase = (uint32_t)(wm*64 + mt*16) * (RS*4);
            uint32_t ah0, ah1, ah2, ah3, al0, al1, al2, al3;
            ldsm4(ah0, ah1, ah2, ah3, aAh + cb + rbase + offA);
            ldsm4(al0, al1, al2, al3, aAl + cb + rbase + offA);
            #pragma unroll
            for (int nt = 0; nt < 4; nt++) {
                mma16(acc[mt][nt][0], acc[mt][nt][1], acc[mt][nt][2], acc[mt][nt][3],
                      ah0, ah1, ah2, ah3, bh[nt][0], bh[nt][1]);
                mma16(acc[mt][nt][0], acc[mt][nt][1], acc[mt][nt][2], acc[mt][nt][3],
                      ah0, ah1, ah2, ah3, bl[nt][0], bl[nt][1]);
                mma16(acc[mt][nt][0], acc[mt][nt][1], acc[mt][nt][2], acc[mt][nt][3],
                      al0, al1, al2, al3, bh[nt][0], bh[nt][1]);
            }
        }
        if (c + 1 < NC) {
            GSTAGE((c+1) & 1);
            if (c + 2 < NC) GLOAD(c+2);
        }
        __syncthreads();
    }
    #undef GLOAD
    #undef GSTAGE

    if (mode <= 1) {
        uint2* O = (mode == 0) ? g_qp : g_kp;
        #pragma unroll
        for (int mt = 0; mt < 4; mt++) {
            int r = m0 + wm*64 + mt*16 + qr;
            #pragma unroll
            for (int nt = 0; nt < 4; nt++) {
                int colp = (n0 >> 1) + wn*16 + nt*4 + qc;
                uint2 pk;
                split2(acc[mt][nt][0]*scale, acc[mt][nt][1]*scale, pk.x, pk.y);
                O[(size_t)r*CDP + colp] = pk;
                split2(acc[mt][nt][2]*scale, acc[mt][nt][3]*scale, pk.x, pk.y);
                O[(size_t)(r+8)*CDP + colp] = pk;
            }
        }
    } else {
        float* O = (mode == 2) ? g_v : g_gate;
        #pragma unroll
        for (int mt = 0; mt < 4; mt++) {
            int r = m0 + wm*64 + mt*16 + qr;
            #pragma unroll
            for (int nt = 0; nt < 4; nt++) {
                int col = n0 + wn*32 + nt*8 + qc*2;
                float o0 = acc[mt][nt][0], o1 = acc[mt][nt][1];
                float o2 = acc[mt][nt][2], o3 = acc[mt][nt][3];
                if (mode == 3) {
                    float b0 = bg[col], b1 = bg[col+1];
                    o0 = 1.0f/(1.0f + __expf(-(o0+b0)));
                    o1 = 1.0f/(1.0f + __expf(-(o1+b1)));
                    o2 = 1.0f/(1.0f + __expf(-(o2+b0)));
                    o3 = 1.0f/(1.0f + __expf(-(o3+b1)));
                }
                *(float2*)(O + (size_t)r*CD + col)     = make_float2(o0, o1);
                *(float2*)(O + (size_t)(r+8)*CD + col) = make_float2(o2, o3);
            }
        }
    }
}

// ---------------- scores + stats: single-shot staging, coalesced P ----------
#define PTS 68   // P-tile row stride in uint32 (16B-aligned, conflict-free)
__global__ __launch_bounds__(256, 2)
void scores_stats()
{
    extern __shared__ uint32_t SM[];   // 96KB dynamic: 4 chunk-buffers, then P-tile
    const uint32_t BUF = 128*RS*4;
    uint32_t aAh = s2u(SM);
    uint32_t aAl = aAh + 4*BUF;
    uint32_t aBh = aAh + 8*BUF;
    uint32_t aBl = aAh + 12*BUF;
    int z = blockIdx.z, b = z >> 3, h = z & 7;
    int m0 = blockIdx.y * 128, n0 = blockIdx.x * 128;
    int tid = threadIdx.x, wid = tid >> 5, lane = tid & 31;
    int wm = wid & 1, wn = wid >> 1;
    int lr = tid >> 2, kp = (tid & 3) * 2;
    int qr = lane >> 2, qc = lane & 3;

    const uint2* Ag = g_qp + (size_t)(b*CS + m0)*CDP + h*32;
    const uint2* Bg = g_kp + (size_t)(b*CS + n0)*CDP + h*32;

    uint32_t offA = (uint32_t)(lane & 15) * (RS*4) + (uint32_t)((lane >> 4) & 1) * 16;
    uint32_t offB = (uint32_t)((lane & 7) + ((lane >> 4) & 1) * 8) * (RS*4)
                  + (uint32_t)((lane >> 3) & 1) * 16;

    float acc[4][4][4];
    #pragma unroll
    for (int i = 0; i < 4; i++)
        #pragma unroll
        for (int j = 0; j < 4; j++)
            #pragma unroll
            for (int e = 0; e < 4; e++) acc[i][j][e] = 0.f;

    #define SSTORE(addr, v2_) asm volatile("st.shared.v2.u32 [%0], {%1,%2};" \
        :: "r"(addr), "r"((v2_).x), "r"((v2_).y) : "memory")
    // stage all 4 chunks (K=64) once
    #pragma unroll
    for (int c = 0; c < 4; c++) {
        size_t o0_ = (size_t)lr*CDP + (size_t)c*8 + kp;
        size_t o1_ = (size_t)(lr+64)*CDP + (size_t)c*8 + kp;
        uint4 rA0 = *(const uint4*)(Ag + o0_), rA1 = *(const uint4*)(Ag + o1_);
        uint4 rB0 = *(const uint4*)(Bg + o0_), rB1 = *(const uint4*)(Bg + o1_);
        uint32_t rowb  = (uint32_t)lr*(RS*4) + (uint32_t)kp*4 + (uint32_t)c*BUF;
        uint32_t rowb2 = rowb + 64*(RS*4);
        SSTORE(aAh + rowb,  make_uint2(rA0.x, rA0.z));
        SSTORE(aAl + rowb,  make_uint2(rA0.y, rA0.w));
        SSTORE(aAh + rowb2, make_uint2(rA1.x, rA1.z));
        SSTORE(aAl + rowb2, make_uint2(rA1.y, rA1.w));
        SSTORE(aBh + rowb,  make_uint2(rB0.x, rB0.z));
        SSTORE(aBl + rowb,  make_uint2(rB0.y, rB0.w));
        SSTORE(aBh + rowb2, make_uint2(rB1.x, rB1.z));
        SSTORE(aBl + rowb2, make_uint2(rB1.y, rB1.w));
    }
    #undef SSTORE
    __syncthreads();

    #pragma unroll
    for (int c = 0; c < 4; c++) {
        uint32_t cb = (uint32_t)c * BUF;
        uint32_t bh[4][2], bl[4][2];
        #pragma unroll
        for (int ntp = 0; ntp < 2; ntp++) {
            uint32_t nbase = (uint32_t)(wn*32 + ntp*16) * (RS*4);
            ldsm4(bh[2*ntp][0], bh[2*ntp][1], bh[2*ntp+1][0], bh[2*ntp+1][1], aBh + cb + nbase + offB);
            ldsm4(bl[2*ntp][0], bl[2*ntp][1], bl[2*ntp+1][0], bl[2*ntp+1][1], aBl + cb + nbase + offB);
        }
        #pragma unroll
        for (int mt = 0; mt < 4; mt++) {
            uint32_t rbase = (uint32_t)(wm*64 + mt*16) * (RS*4);
            uint32_t ah0, ah1, ah2, ah3, al0, al1, al2, al3;
            ldsm4(ah0, ah1, ah2, ah3, aAh + cb + rbase + offA);
            ldsm4(al0, al1, al2, al3, aAl + cb + rbase + offA);
            #pragma unroll
            for (int nt = 0; nt < 4; nt++) {
                mma16(acc[mt][nt][0], acc[mt][nt][1], acc[mt][nt][2], acc[mt][nt][3],
                      ah0, ah1, ah2, ah3, bh[nt][0], bh[nt][1]);
                mma16(acc[mt][nt][0], acc[mt][nt][1], acc[mt][nt][2], acc[mt][nt][3],
                      ah0, ah1, ah2, ah3, bl[nt][0], bl[nt][1]);
                mma16(acc[mt][nt][0], acc[mt][nt][1], acc[mt][nt][2], acc[mt][nt][3],
                      al0, al1, al2, al3, bh[nt][0], bh[nt][1]);
            }
        }
    }
    __syncthreads();   // staging buffers dead; P-tile reuse below

    // epilogue: ex = exp(x); stats; P -> SMEM tile, then coalesced stores
    uint32_t* Pt = SM;   // [128][PTS]
    float csl[4][2];
    #pragma unroll
    for (int nt = 0; nt < 4; nt++) { csl[nt][0] = 0.f; csl[nt][1] = 0.f; }
    #pragma unroll
    for (int mt = 0; mt < 4; mt++) {
        float ex[4][4];
        #pragma unroll
        for (int nt = 0; nt < 4; nt++)
            #pragma unroll
            for (int e = 0; e < 4; e++) ex[nt][e] = fast_exp(acc[mt][nt][e]);
        float r0 = 0.f, r1 = 0.f;
        #pragma unroll
        for (int nt = 0; nt < 4; nt++) {
            r0 += ex[nt][0] + ex[nt][1];
            r1 += ex[nt][2] + ex[nt][3];
            csl[nt][0] += ex[nt][0] + ex[nt][2];
            csl[nt][1] += ex[nt][1] + ex[nt][3];
        }
        r0 += __shfl_xor_sync(0xffffffffu, r0, 1);
        r0 += __shfl_xor_sync(0xffffffffu, r0, 2);
        r1 += __shfl_xor_sync(0xffffffffu, r1, 1);
        r1 += __shfl_xor_sync(0xffffffffu, r1, 2);
        int lrow0 = wm*64 + mt*16 + qr;
        if (qc == 0) {
            int rslot = blockIdx.x * 4 + wn;
            g_rpart[((size_t)(z*CS + m0 + lrow0) << 6) + rslot]     = r0;
            g_rpart[((size_t)(z*CS + m0 + lrow0 + 8) << 6) + rslot] = r1;
        }
        #pragma unroll
        for (int nt = 0; nt < 4; nt++) {
            int pc_ = wn*16 + nt*4 + qc;
            Pt[lrow0*PTS + pc_]       = pack_h2(ex[nt][0]*ex[nt][0]*PSCALE,
                                                ex[nt][1]*ex[nt][1]*PSCALE);
            Pt[(lrow0 + 8)*PTS + pc_] = pack_h2(ex[nt][2]*ex[nt][2]*PSCALE,
                                                ex[nt][3]*ex[nt][3]*PSCALE);
        }
    }
    #pragma unroll
    for (int nt = 0; nt < 4; nt++) {
        #pragma unroll
        for (int j = 0; j < 2; j++) {
            float v = csl[nt][j];
            v += __shfl_xor_sync(0xffffffffu, v, 4);
            v += __shfl_xor_sync(0xffffffffu, v, 8);
            v += __shfl_xor_sync(0xffffffffu, v, 16);
            if (qr == 0) {
                int cslot = blockIdx.y * 2 + wm;
                int col = n0 + wn*32 + nt*8 + qc*2 + j;
                g_cpart[((size_t)(z*CS + col) << 5) + cslot] = v;
            }
        }
    }
    __syncthreads();
    #pragma unroll
    for (int i = 0; i < 8; i++) {
        int idx = tid + i*256;
        int row = idx >> 4, c4 = (idx & 15) * 4;
        uint4 v = *(uint4*)&Pt[row*PTS + c4];
        *(uint4*)(g_p + (size_t)(z*CS + m0 + row)*CSP + (n0 >> 1) + c4) = v;
    }
}

// ---------------- finalize: reduce partials -> reciprocals ------------------
__global__ __launch_bounds__(256)
void finalize_kernel()
{
    int i = blockIdx.x * 256 + threadIdx.x;
    if (i < CBH*CS) {
        const float4* p = (const float4*)(g_rpart + ((size_t)i << 6));
        float s = 0.f;
        #pragma unroll
        for (int j = 0; j < 16; j++) {
            float4 v = p[j];
            s += v.x + v.y + v.z + v.w;
        }
        g_rsum[i] = 1.0f / s;
    } else {
        i -= CBH*CS;
        const float4* p = (const float4*)(g_cpart + ((size_t)i << 5));
        float s = 0.f;
        #pragma unroll
        for (int j = 0; j < 8; j++) {
            float4 v = p[j];
            s += v.x + v.y + v.z + v.w;
        }
        g_csum[i] = 1.0f / s;
    }
}

// ---------------- V transpose: ci*256 folded, single fp16 -------------------
__global__ __launch_bounds__(256)
void vtrans_ci()
{
    __shared__ float tile[64][65];
    int z = blockIdx.y, b = z >> 3, h = z & 7;
    int t0 = blockIdx.x * 64;
    const float* src = g_v + (size_t)b*CS*CD + h*CDK;
    int tid = threadIdx.x;
    #pragma unroll
    for (int i = 0; i < 16; i++) {
        int idx = tid + i*256;
        int tr = idx >> 6, d = idx & 63;
        tile[tr][d] = src[(size_t)(t0 + tr)*CD + d] * (g_csum[z*CS + t0 + tr] * VSCALE);
    }
    __syncthreads();
    #pragma unroll
    for (int i = 0; i < 8; i++) {
        int idx = tid + i*256;
        int d = idx >> 5, tp = idx & 31;
        g_vt1[((size_t)z*CDK + d)*CSP + (t0 >> 1) + tp] =
            pack_h2(tile[2*tp][d], tile[2*tp+1][d]);
    }
}

// ---------------- PV: fp16 P x fp16 V (single), fp16 out --------------------
__global__ __launch_bounds__(256)
void pv_kernel()
{
    __shared__ uint32_t Ph[2][128][RS];
    __shared__ uint32_t Vh[2][64][RS];
    int z = blockIdx.y, b = z >> 3, h = z & 7;
    int s0 = blockIdx.x * 128;
    int tid = threadIdx.x, wid = tid >> 5, lane = tid & 31;
    int wm = wid & 3, wn = wid >> 2;
    int qr = lane >> 2, qc = lane & 3;

    int pr = tid >> 1;                 // P row 0..127
    int pp = (tid & 1) * 4;            // uint32 base 0/4 within 8-u32 chunk row
    int vr = tid >> 2;                 // V^T row (dk) 0..63
    int vp = (tid & 3) * 2;            // pair base 0,2,4,6
    const uint32_t* aph = g_p   + (size_t)(z*CS + s0 + pr)*CSP;
    const uint32_t* avh = g_vt1 + ((size_t)z*CDK + vr)*CSP;

    const uint32_t BUFP = 128*RS*4, BUFV = 64*RS*4;
    uint32_t aPh = s2u(Ph), aVh = s2u(Vh);
    uint32_t offA = (uint32_t)(lane & 15) * (RS*4) + (uint32_t)((lane >> 4) & 1) * 16;
    uint32_t offB = (uint32_t)((lane & 7) + ((lane >> 4) & 1) * 8) * (RS*4)
                  + (uint32_t)((lane >> 3) & 1) * 16;

    float acc[2][4][4];
    #pragma unroll
    for (int i = 0; i < 2; i++)
        #pragma unroll
        for (int j = 0; j < 4; j++)
            #pragma unroll
            for (int e = 0; e < 4; e++) acc[i][j][e] = 0.f;

    uint4 rp0; uint2 rv0;
    #define PLOAD(c) do { \
        rp0 = *(const uint4*)(aph + (size_t)(c)*8 + pp); \
        rv0 = *(const uint2*)(avh + (size_t)(c)*8 + vp); \
    } while (0)
    #define PSTAGE(bi) do { \
        *(uint4*)&Ph[bi][pr][pp] = rp0; \
        *(uint2*)&Vh[bi][vr][vp] = rv0; \
    } while (0)

    const int NC = CS / 16;            // 128 chunks
    PLOAD(0); PSTAGE(0); PLOAD(1);
    __syncthreads();

    for (int c = 0; c < NC; c++) {
        uint32_t cbP = (uint32_t)(c & 1) * BUFP;
        uint32_t cbV = (uint32_t)(c & 1) * BUFV;
        uint32_t bh[4][2];
        #pragma unroll
        for (int ntp = 0; ntp < 2; ntp++) {
            uint32_t nbase = (uint32_t)(wn*32 + ntp*16) * (RS*4);
            ldsm4(bh[2*ntp][0], bh[2*ntp][1], bh[2*ntp+1][0], bh[2*ntp+1][1], aVh + cbV + nbase + offB);
        }
        #pragma unroll
        for (int mt = 0; mt < 2; mt++) {
            uint32_t rbase = (uint32_t)(wm*32 + mt*16) * (RS*4);
            uint32_t a0, a1, a2, a3;
            ldsm4(a0, a1, a2, a3, aPh + cbP + rbase + offA);
            #pragma unroll
            for (int nt = 0; nt < 4; nt++)
                mma16h(acc[mt][nt][0], acc[mt][nt][1], acc[mt][nt][2], acc[mt][nt][3],
                       a0, a1, a2, a3, bh[nt][0], bh[nt][1]);
        }
        if (c + 1 < NC) {
            PSTAGE((c+1) & 1);
            if (c + 2 < NC) PLOAD(c+2);
        }
        __syncthreads();
    }
    #undef PLOAD
    #undef PSTAGE
    // epilogue: * rsum_inv, * gate -> g_aop1 (single fp16 pairs)
    #pragma unroll
    for (int mt = 0; mt < 2; mt++) {
        #pragma unroll
        for (int half = 0; half < 2; half++) {
            int srow = s0 + wm*32 + mt*16 + qr + half*8;
            float ri = g_rsum[(size_t)z*CS + srow];
            const float* grow = g_gate + ((size_t)b*CS + srow)*CD + h*CDK;
            uint32_t* orow    = g_aop1 + ((size_t)b*CS + srow)*CDP + h*32;
            #pragma unroll
            for (int nt = 0; nt < 4; nt++) {
                int col = wn*32 + nt*8 + qc*2;
                float2 gg = *(const float2*)(grow + col);
                float o0 = acc[mt][nt][half*2+0] * ri * gg.x;
                float o1 = acc[mt][nt][half*2+1] * ri * gg.y;
                orow[col >> 1] = pack_h2(o0, o1);
            }
        }
    }
}

// ---------------- output projection: fp16 A (single) x fp16 Wo (split) ------
__global__ __launch_bounds__(256, 2)
void out_gemm(const float* __restrict__ bo, float* __restrict__ C)
{
    __shared__ uint32_t Ah[2][128][RS];
    __shared__ uint32_t Bh[2][128][RS], Bl[2][128][RS];
    int tid = threadIdx.x, wid = tid >> 5, lane = tid & 31;
    int wm = wid & 1, wn = wid >> 1;
    int m0 = blockIdx.y * 128, n0 = blockIdx.x * 128;
    const uint32_t* Ag = g_aop1 + (size_t)m0 * CDP;
    const uint2*    Bg = g_wp[4] + (size_t)n0 * CDP;
    int lr = tid >> 2, kp = (tid & 3) * 2;
    int qr = lane >> 2, qc = lane & 3;

    const uint32_t BUF = 128*RS*4;
    uint32_t aAh = s2u(Ah), aBh = s2u(Bh), aBl = s2u(Bl);
    uint32_t offA = (uint32_t)(lane & 15) * (RS*4) + (uint32_t)((lane >> 4) & 1) * 16;
    uint32_t offB = (uint32_t)((lane & 7) + ((lane >> 4) & 1) * 8) * (RS*4)
                  + (uint32_t)((lane >> 3) & 1) * 16;

    float acc[4][4][4];
    #pragma unroll
    for (int i = 0; i < 4; i++)
        #pragma unroll
        for (int j = 0; j < 4; j++)
            #pragma unroll
            for (int e = 0; e < 4; e++) acc[i][j][e] = 0.f;

    uint2 rA0, rA1; uint4 rB0, rB1;
    #define OLOAD(c) do { \
        size_t o0_ = (size_t)lr*CDP + (size_t)(c)*8 + kp; \
        size_t o1_ = (size_t)(lr+64)*CDP + (size_t)(c)*8 + kp; \
        rA0 = *(const uint2*)(Ag + o0_); rA1 = *(const uint2*)(Ag + o1_); \
        rB0 = *(const uint4*)(Bg + o0_); rB1 = *(const uint4*)(Bg + o1_); \
    } while (0)
    #define OSTAGE(bi) do { \
        *(uint2*)&Ah[bi][lr][kp]    = rA0; \
        *(uint2*)&Ah[bi][lr+64][kp] = rA1; \
        *(uint2*)&Bh[bi][lr][kp]    = make_uint2(rB0.x, rB0.z); \
        *(uint2*)&Bl[bi][lr][kp]    = make_uint2(rB0.y, rB0.w); \
        *(uint2*)&Bh[bi][lr+64][kp] = make_uint2(rB1.x, rB1.z); \
        *(uint2*)&Bl[bi][lr+64][kp] = make_uint2(rB1.y, rB1.w); \
    } while (0)

    const int NC = CD / 16;
    OLOAD(0); OSTAGE(0); OLOAD(1);
    __syncthreads();

    for (int c = 0; c < NC; c++) {
        uint32_t cb = (uint32_t)(c & 1) * BUF;
        uint32_t bh[4][2], bl[4][2];
        #pragma unroll
        for (int ntp = 0; ntp < 2; ntp++) {
            uint32_t nbase = (uint32_t)(wn*32 + ntp*16) * (RS*4);
            ldsm4(bh[2*ntp][0], bh[2*ntp][1], bh[2*ntp+1][0], bh[2*ntp+1][1], aBh + cb + nbase + offB);
            ldsm4(bl[2*ntp][0], bl[2*ntp][1], bl[2*ntp+1][0], bl[2*ntp+1][1], aBl + cb + nbase + offB);
        }
        #pragma unroll
        for (int mt = 0; mt < 4; mt++) {
            uint32_t rbase = (uint32_t)(wm*64 + mt*16) * (RS*4);
            uint32_t a0, a1, a2, a3;
            ldsm4(a0, a1, a2, a3, aAh + cb + rbase + offA);
            #pragma unroll
            for (int nt = 0; nt < 4; nt++) {
                mma16h(acc[mt][nt][0], acc[mt][nt][1], acc[mt][nt][2], acc[mt][nt][3],
                       a0, a1, a2, a3, bh[nt][0], bh[nt][1]);
                mma16h(acc[mt][nt][0], acc[mt][nt][1], acc[mt][nt][2], acc[mt][nt][3],
                       a0, a1, a2, a3, bl[nt][0], bl[nt][1]);
            }
        }
        if (c + 1 < NC) {
            OSTAGE((c+1) & 1);
            if (c + 2 < NC) OLOAD(c+2);
        }
        __syncthreads();
    }
    #undef OLOAD
    #undef OSTAGE
    #pragma unroll
    for (int mt = 0; mt < 4; mt++) {
        int r = m0 + wm*64 + mt*16 + qr;
        #pragma unroll
        for (int nt = 0; nt < 4; nt++) {
            int col = n0 + wn*32 + nt*8 + qc*2;
            float b0 = bo[col], b1 = bo[col+1];
            *(float2*)(C + (size_t)r*CD + col) =
                make_float2(acc[mt][nt][0] + b0, acc[mt][nt][1] + b1);
            *(float2*)(C + (size_t)(r+8)*CD + col) =
                make_float2(acc[mt][nt][2] + b0, acc[mt][nt][3] + b1);
        }
    }
}

// ---------------- launch ----------------
extern "C" void kernel_launch(void* const* d_in, const int* in_sizes, int n_in,
                              void* d_out, int out_size)
{
    const float* x_q   = (const float*)d_in[0];
    const float* x_k   = (const float*)d_in[1];
    const float* Wq    = (const float*)d_in[2];
    const float* Wk    = (const float*)d_in[3];
    const float* Wv    = (const float*)d_in[4];
    const float* Wg    = (const float*)d_in[5];
    const float* bg    = (const float*)d_in[6];
    const float* Wo    = (const float*)d_in[7];
    const float* bo    = (const float*)d_in[8];
    const float* gamma = (const float*)d_in[9];
    const float* beta  = (const float*)d_in[10];
    float* out = (float*)d_out;

    const int SM_SCORES = 16*128*RS*4;   // 96KB
    cudaFuncSetAttribute(scores_stats,
                         cudaFuncAttributeMaxDynamicSharedMemorySize, SM_SCORES);

    // 1. LayerNorm (packed-split output) + weight split
    ln_kernel<<<2*CM, 256>>>(x_q, x_k, gamma, beta);
    wsplit_kernel<<<dim3(CD*CDP/256, 5), 256>>>(Wq, Wk, Wv, Wg, Wo);

    // 2. All projections, one launch (copy-staged)
    proj_all<<<dim3(CD/128, CM/128, 4), 256>>>(bg);

    // 3. Scores + stats: single-shot staging, coalesced fp16 P stores
    scores_stats<<<dim3(CS/128, CS/128, CBH), 256, SM_SCORES>>>();

    // 4. Reduce partials -> reciprocal sums
    finalize_kernel<<<(2*CBH*CS)/256, 256>>>();

    // 5. V transpose with ci*256 folded, single fp16
    vtrans_ci<<<dim3(CS/64, CBH), 256>>>();

    // 6. PV: single fp16 MMA per tile, fp16 out
    pv_kernel<<<dim3(CS/128, CBH), 256>>>();

    // 7. Output projection (fp16 A x fp16-split Wo) + bias -> d_out
    out_gemm<<<dim3(CD/128, CM/128), 256>>>(bo, out);
}

// round 16
// speedup vs baseline: 1.5607x; 1.0047x over previous
#include <cuda_runtime.h>
#include <cuda_bf16.h>
#include <cuda_fp16.h>
#include <cstdint>
#include <math.h>

#define CB 4
#define CS 2048
#define CD 512
#define CH 8
#define CDK 64
#define CM (CB*CS)      // 8192
#define CBH (CB*CH)     // 32
#define CDP (CD/2)      // 256 pairs per D row
#define CSP (CS/2)      // 1024 pairs per score row

#define PSCALE (1.0f/256.0f)
#define VSCALE 256.0f

// ---------------- scratch (device globals: allocation-free) ----------------
static __device__ uint2 g_xqp[CM*CDP];                // LN(xq) fp16 split
static __device__ uint2 g_xkp[CM*CDP];                // LN(xk) fp16 split
static __device__ uint2 g_wp[5][CD*CDP];              // weights fp16 split
static __device__ uint2 g_qp[CM*CDP];                 // q/8 fp16 split
static __device__ uint32_t g_kp1[CM*CDP];             // k single fp16 pairs
static __device__ float g_v[CM*CD];
static __device__ float g_gate[CM*CD];
static __device__ uint32_t g_aop1[CM*CDP];            // attn-out*ri*gate fp16 pairs
static __device__ uint32_t g_p[(size_t)CBH*CS*CSP];   // fp16x2: exp(2x)*2^-8
static __device__ uint32_t g_vt1[CBH*CDK*CSP];        // fp16x2: V^T*ci*2^8
static __device__ float g_rpart[(size_t)CBH*CS*64];
static __device__ float g_cpart[(size_t)CBH*CS*32];
static __device__ float g_rsum[CBH*CS];
static __device__ float g_csum[CBH*CS];

// ---------------- helpers ----------------
__device__ __forceinline__ uint32_t s2u(const void* p) {
    return (uint32_t)__cvta_generic_to_shared(p);
}
__device__ __forceinline__ uint32_t pack_h2(float x0, float x1) {
    __half2 h = __floats2half2_rn(x0, x1);
    return *(uint32_t*)&h;
}
__device__ __forceinline__ void splith2(float x0, float x1, uint32_t &hi, uint32_t &lo) {
    __half h0 = __float2half_rn(x0);
    __half h1 = __float2half_rn(x1);
    float r0 = x0 - __half2float(h0);
    float r1 = x1 - __half2float(h1);
    __half l0 = __float2half_rn(r0);
    __half l1 = __float2half_rn(r1);
    hi = (uint32_t)__half_as_ushort(h0) | ((uint32_t)__half_as_ushort(h1) << 16);
    lo = (uint32_t)__half_as_ushort(l0) | ((uint32_t)__half_as_ushort(l1) << 16);
}
__device__ __forceinline__ void mma16h(float &c0, float &c1, float &c2, float &c3,
                                       uint32_t a0, uint32_t a1, uint32_t a2, uint32_t a3,
                                       uint32_t b0, uint32_t b1) {
    asm("mma.sync.aligned.m16n8k16.row.col.f32.f16.f16.f32 "
        "{%0,%1,%2,%3}, {%4,%5,%6,%7}, {%8,%9}, {%0,%1,%2,%3};"
        : "+f"(c0), "+f"(c1), "+f"(c2), "+f"(c3)
        : "r"(a0), "r"(a1), "r"(a2), "r"(a3), "r"(b0), "r"(b1));
}
__device__ __forceinline__ void ldsm4(uint32_t &r0, uint32_t &r1, uint32_t &r2, uint32_t &r3,
                                      uint32_t addr) {
    asm volatile("ldmatrix.sync.aligned.m8n8.x4.shared.b16 {%0,%1,%2,%3}, [%4];"
                 : "=r"(r0), "=r"(r1), "=r"(r2), "=r"(r3) : "r"(addr));
}
#define RS 12   // SMEM row stride in uint32 (48B, conflict-free)

__device__ __forceinline__ float fast_exp(float x) {
    x = fmaxf(x, -80.0f);
    float t  = x * 1.4426950408889634f;
    float fi = floorf(t);
    float f  = t - fi;
    float p  = 1.53533e-4f;
    p = fmaf(p, f, 1.33989e-3f);
    p = fmaf(p, f, 9.61844e-3f);
    p = fmaf(p, f, 5.55033e-2f);
    p = fmaf(p, f, 2.40226e-1f);
    p = fmaf(p, f, 6.93147e-1f);
    p = fmaf(p, f, 1.0f);
    return __int_as_float(((int)fi + 127) << 23) * p;
}

// ---------------- LayerNorm -> fp16 split ----------------
__global__ __launch_bounds__(256)
void ln_kernel(const float* __restrict__ xq, const float* __restrict__ xk,
               const float* __restrict__ gamma, const float* __restrict__ beta)
{
    int row = blockIdx.x;
    const float* x; uint2* o;
    if (row < CM) { x = xq + (size_t)row*CD;       o = g_xqp + (size_t)row*CDP; }
    else          { x = xk + (size_t)(row-CM)*CD;  o = g_xkp + (size_t)(row-CM)*CDP; }
    int t = threadIdx.x;
    float2 v2 = ((const float2*)x)[t];
    float s  = v2.x + v2.y;
    float ss = v2.x*v2.x + v2.y*v2.y;
    #pragma unroll
    for (int off = 16; off; off >>= 1) {
        s  += __shfl_xor_sync(0xffffffffu, s,  off);
        ss += __shfl_xor_sync(0xffffffffu, ss, off);
    }
    __shared__ float sh_s[8], sh_ss[8];
    __shared__ float s_mean, s_rstd;
    int wid = t >> 5, lid = t & 31;
    if (lid == 0) { sh_s[wid] = s; sh_ss[wid] = ss; }
    __syncthreads();
    if (t < 32) {
        float a = (t < 8) ? sh_s[t]  : 0.f;
        float b = (t < 8) ? sh_ss[t] : 0.f;
        #pragma unroll
        for (int off = 4; off; off >>= 1) {
            a += __shfl_xor_sync(0xffffffffu, a, off);
            b += __shfl_xor_sync(0xffffffffu, b, off);
        }
        if (t == 0) {
            float mean = a * (1.0f/CD);
            float var  = b * (1.0f/CD) - mean*mean;
            s_mean = mean;
            s_rstd = rsqrtf(var + 1e-6f);
        }
    }
    __syncthreads();
    float mean = s_mean, rstd = s_rstd;
    float2 g2 = ((const float2*)gamma)[t];
    float2 b2 = ((const float2*)beta)[t];
    float o0 = (v2.x - mean) * rstd * g2.x + b2.x;
    float o1 = (v2.y - mean) * rstd * g2.y + b2.y;
    uint2 pk;
    splith2(o0, o1, pk.x, pk.y);
    o[t] = pk;
}

// ---------------- weight split: all fp16 ----------------
__global__ __launch_bounds__(256)
void wsplit_kernel(const float* __restrict__ Wq, const float* __restrict__ Wk,
                   const float* __restrict__ Wv, const float* __restrict__ Wg,
                   const float* __restrict__ Wo)
{
    int m = blockIdx.y;
    const float* W = (m == 0) ? Wq : (m == 1) ? Wk : (m == 2) ? Wv : (m == 3) ? Wg : Wo;
    int idx = blockIdx.x * 256 + threadIdx.x;
    float2 v = ((const float2*)W)[idx];
    uint2 pk;
    splith2(v.x, v.y, pk.x, pk.y);
    g_wp[m][idx] = pk;
}

// ---------------- merged projections (fp16) ---------------------------------
// modes 0,1 (q,k): 3-term fp16 (2^-22). modes 2,3 (v,gate): 2-term.
__global__ __launch_bounds__(256, 2)
void proj_all(const float* __restrict__ bg)
{
    __shared__ uint32_t Ah[2][128][RS], Al[2][128][RS];
    __shared__ uint32_t Bh[2][128][RS], Bl[2][128][RS];
    int mode = blockIdx.z;
    bool fullB = (mode <= 1);
    const uint2* A = (mode == 0 || mode == 3) ? g_xqp : g_xkp;
    const uint2* B = g_wp[mode];
    float scale = (mode == 0) ? 0.125f : 1.0f;

    int tid = threadIdx.x, wid = tid >> 5, lane = tid & 31;
    int wm = wid & 1, wn = wid >> 1;
    int m0 = blockIdx.y * 128, n0 = blockIdx.x * 128;
    const uint2* Ag = A + (size_t)m0 * CDP;
    const uint2* Bg = B + (size_t)n0 * CDP;
    int lr = tid >> 2, kp = (tid & 3) * 2;
    int qr = lane >> 2, qc = lane & 3;

    const uint32_t BUF = 128*RS*4;
    uint32_t aAh = s2u(Ah), aAl = s2u(Al), aBh = s2u(Bh), aBl = s2u(Bl);
    uint32_t offA = (uint32_t)(lane & 15) * (RS*4) + (uint32_t)((lane >> 4) & 1) * 16;
    uint32_t offB = (uint32_t)((lane & 7) + ((lane >> 4) & 1) * 8) * (RS*4)
                  + (uint32_t)((lane >> 3) & 1) * 16;

    float acc[4][4][4];
    #pragma unroll
    for (int i = 0; i < 4; i++)
        #pragma unroll
        for (int j = 0; j < 4; j++)
            #pragma unroll
            for (int e = 0; e < 4; e++) acc[i][j][e] = 0.f;

    uint4 rA0, rA1, rB0, rB1;
    #define GLOAD(c) do { \
        size_t o0_ = (size_t)lr*CDP + (size_t)(c)*8 + kp; \
        size_t o1_ = (size_t)(lr+64)*CDP + (size_t)(c)*8 + kp; \
        rA0 = *(const uint4*)(Ag + o0_); rA1 = *(const uint4*)(Ag + o1_); \
        rB0 = *(const uint4*)(Bg + o0_); rB1 = *(const uint4*)(Bg + o1_); \
    } while (0)
    #define GSTAGE(bi) do { \
        *(uint2*)&Ah[bi][lr][kp]    = make_uint2(rA0.x, rA0.z); \
        *(uint2*)&Al[bi][lr][kp]    = make_uint2(rA0.y, rA0.w); \
        *(uint2*)&Ah[bi][lr+64][kp] = make_uint2(rA1.x, rA1.z); \
        *(uint2*)&Al[bi][lr+64][kp] = make_uint2(rA1.y, rA1.w); \
        *(uint2*)&Bh[bi][lr][kp]    = make_uint2(rB0.x, rB0.z); \
        *(uint2*)&Bh[bi][lr+64][kp] = make_uint2(rB1.x, rB1.z); \
        if (fullB) { \
            *(uint2*)&Bl[bi][lr][kp]    = make_uint2(rB0.y, rB0.w); \
            *(uint2*)&Bl[bi][lr+64][kp] = make_uint2(rB1.y, rB1.w); \
        } \
    } while (0)

    const int NC = CD / 16;    // 32
    GLOAD(0); GSTAGE(0); GLOAD(1);
    __syncthreads();

    for (int c = 0; c < NC; c++) {
        uint32_t cb = (uint32_t)(c & 1) * BUF;
        uint32_t bh[4][2], bl[4][2];
        #pragma unroll
        for (int ntp = 0; ntp < 2; ntp++) {
            uint32_t nbase = (uint32_t)(wn*32 + ntp*16) * (RS*4);
            ldsm4(bh[2*ntp][0], bh[2*ntp][1], bh[2*ntp+1][0], bh[2*ntp+1][1], aBh + cb + nbase + offB);
            if (fullB)
                ldsm4(bl[2*ntp][0], bl[2*ntp][1], bl[2*ntp+1][0], bl[2*ntp+1][1], aBl + cb + nbase + offB);
        }
        #pragma unroll
        for (int mt = 0; mt < 4; mt++) {
            uint32_t rbase = (uint32_t)(wm*64 + mt*16) * (RS*4);
            uint32_t ah0, ah1, ah2, ah3, al0, al1, al2, al3;
            ldsm4(ah0, ah1, ah2, ah3, aAh + cb + rbase + offA);
            ldsm4(al0, al1, al2, al3, aAl + cb + rbase + offA);
            #pragma unroll
            for (int nt = 0; nt < 4; nt++) {
                mma16h(acc[mt][nt][0], acc[mt][nt][1], acc[mt][nt][2], acc[mt][nt][3],
                       ah0, ah1, ah2, ah3, bh[nt][0], bh[nt][1]);
                mma16h(acc[mt][nt][0], acc[mt][nt][1], acc[mt][nt][2], acc[mt][nt][3],
                       al0, al1, al2, al3, bh[nt][0], bh[nt][1]);
                if (fullB)
                    mma16h(acc[mt][nt][0], acc[mt][nt][1], acc[mt][nt][2], acc[mt][nt][3],
                           ah0, ah1, ah2, ah3, bl[nt][0], bl[nt][1]);
            }
        }
        if (c + 1 < NC) {
            GSTAGE((c+1) & 1);
            if (c + 2 < NC) GLOAD(c+2);
        }
        __syncthreads();
    }
    #undef GLOAD
    #undef GSTAGE

    if (mode == 0) {
        #pragma unroll
        for (int mt = 0; mt < 4; mt++) {
            int r = m0 + wm*64 + mt*16 + qr;
            #pragma unroll
            for (int nt = 0; nt < 4; nt++) {
                int colp = (n0 >> 1) + wn*16 + nt*4 + qc;
                uint2 pk;
                splith2(acc[mt][nt][0]*scale, acc[mt][nt][1]*scale, pk.x, pk.y);
                g_qp[(size_t)r*CDP + colp] = pk;
                splith2(acc[mt][nt][2]*scale, acc[mt][nt][3]*scale, pk.x, pk.y);
                g_qp[(size_t)(r+8)*CDP + colp] = pk;
            }
        }
    } else if (mode == 1) {
        #pragma unroll
        for (int mt = 0; mt < 4; mt++) {
            int r = m0 + wm*64 + mt*16 + qr;
            #pragma unroll
            for (int nt = 0; nt < 4; nt++) {
                int colp = (n0 >> 1) + wn*16 + nt*4 + qc;
                g_kp1[(size_t)r*CDP + colp]     = pack_h2(acc[mt][nt][0], acc[mt][nt][1]);
                g_kp1[(size_t)(r+8)*CDP + colp] = pack_h2(acc[mt][nt][2], acc[mt][nt][3]);
            }
        }
    } else {
        float* O = (mode == 2) ? g_v : g_gate;
        #pragma unroll
        for (int mt = 0; mt < 4; mt++) {
            int r = m0 + wm*64 + mt*16 + qr;
            #pragma unroll
            for (int nt = 0; nt < 4; nt++) {
                int col = n0 + wn*32 + nt*8 + qc*2;
                float o0 = acc[mt][nt][0], o1 = acc[mt][nt][1];
                float o2 = acc[mt][nt][2], o3 = acc[mt][nt][3];
                if (mode == 3) {
                    float b0 = bg[col], b1 = bg[col+1];
                    o0 = 1.0f/(1.0f + __expf(-(o0+b0)));
                    o1 = 1.0f/(1.0f + __expf(-(o1+b1)));
                    o2 = 1.0f/(1.0f + __expf(-(o2+b0)));
                    o3 = 1.0f/(1.0f + __expf(-(o3+b1)));
                }
                *(float2*)(O + (size_t)r*CD + col)     = make_float2(o0, o1);
                *(float2*)(O + (size_t)(r+8)*CD + col) = make_float2(o2, o3);
            }
        }
    }
}

// ---------------- scores + stats: q split x k single, 2 MMAs ---------------
#define PTS 68   // P-tile row stride in uint32
__global__ __launch_bounds__(256, 2)
void scores_stats()
{
    extern __shared__ uint32_t SM[];   // 72KB: Ah,Al,Bh x4 chunks; then P-tile
    const uint32_t BUF = 128*RS*4;
    uint32_t aAh = s2u(SM);
    uint32_t aAl = aAh + 4*BUF;
    uint32_t aBh = aAh + 8*BUF;
    int z = blockIdx.z, b = z >> 3, h = z & 7;
    int m0 = blockIdx.y * 128, n0 = blockIdx.x * 128;
    int tid = threadIdx.x, wid = tid >> 5, lane = tid & 31;
    int wm = wid & 1, wn = wid >> 1;
    int lr = tid >> 2, kp = (tid & 3) * 2;
    int qr = lane >> 2, qc = lane & 3;

    const uint2*    Ag = g_qp  + (size_t)(b*CS + m0)*CDP + h*32;
    const uint32_t* Bg = g_kp1 + (size_t)(b*CS + n0)*CDP + h*32;

    uint32_t offA = (uint32_t)(lane & 15) * (RS*4) + (uint32_t)((lane >> 4) & 1) * 16;
    uint32_t offB = (uint32_t)((lane & 7) + ((lane >> 4) & 1) * 8) * (RS*4)
                  + (uint32_t)((lane >> 3) & 1) * 16;

    float acc[4][4][4];
    #pragma unroll
    for (int i = 0; i < 4; i++)
        #pragma unroll
        for (int j = 0; j < 4; j++)
            #pragma unroll
            for (int e = 0; e < 4; e++) acc[i][j][e] = 0.f;

    #define SSTORE(addr, v2_) asm volatile("st.shared.v2.u32 [%0], {%1,%2};" \
        :: "r"(addr), "r"((v2_).x), "r"((v2_).y) : "memory")
    #pragma unroll
    for (int c = 0; c < 4; c++) {
        size_t o0_ = (size_t)lr*CDP + (size_t)c*8 + kp;
        size_t o1_ = (size_t)(lr+64)*CDP + (size_t)c*8 + kp;
        uint4 rA0 = *(const uint4*)(Ag + o0_), rA1 = *(const uint4*)(Ag + o1_);
        uint2 rB0 = *(const uint2*)(Bg + o0_), rB1 = *(const uint2*)(Bg + o1_);
        uint32_t rowb  = (uint32_t)lr*(RS*4) + (uint32_t)kp*4 + (uint32_t)c*BUF;
        uint32_t rowb2 = rowb + 64*(RS*4);
        SSTORE(aAh + rowb,  make_uint2(rA0.x, rA0.z));
        SSTORE(aAl + rowb,  make_uint2(rA0.y, rA0.w));
        SSTORE(aAh + rowb2, make_uint2(rA1.x, rA1.z));
        SSTORE(aAl + rowb2, make_uint2(rA1.y, rA1.w));
        SSTORE(aBh + rowb,  rB0);
        SSTORE(aBh + rowb2, rB1);
    }
    #undef SSTORE
    __syncthreads();

    #pragma unroll
    for (int c = 0; c < 4; c++) {
        uint32_t cb = (uint32_t)c * BUF;
        uint32_t bh[4][2];
        #pragma unroll
        for (int ntp = 0; ntp < 2; ntp++) {
            uint32_t nbase = (uint32_t)(wn*32 + ntp*16) * (RS*4);
            ldsm4(bh[2*ntp][0], bh[2*ntp][1], bh[2*ntp+1][0], bh[2*ntp+1][1], aBh + cb + nbase + offB);
        }
        #pragma unroll
        for (int mt = 0; mt < 4; mt++) {
            uint32_t rbase = (uint32_t)(wm*64 + mt*16) * (RS*4);
            uint32_t ah0, ah1, ah2, ah3, al0, al1, al2, al3;
            ldsm4(ah0, ah1, ah2, ah3, aAh + cb + rbase + offA);
            ldsm4(al0, al1, al2, al3, aAl + cb + rbase + offA);
            #pragma unroll
            for (int nt = 0; nt < 4; nt++) {
                mma16h(acc[mt][nt][0], acc[mt][nt][1], acc[mt][nt][2], acc[mt][nt][3],
                       ah0, ah1, ah2, ah3, bh[nt][0], bh[nt][1]);
                mma16h(acc[mt][nt][0], acc[mt][nt][1], acc[mt][nt][2], acc[mt][nt][3],
                       al0, al1, al2, al3, bh[nt][0], bh[nt][1]);
            }
        }
    }
    __syncthreads();   // staging dead; P-tile reuse

    uint32_t* Pt = SM;   // [128][PTS]
    float csl[4][2];
    #pragma unroll
    for (int nt = 0; nt < 4; nt++) { csl[nt][0] = 0.f; csl[nt][1] = 0.f; }
    #pragma unroll
    for (int mt = 0; mt < 4; mt++) {
        float ex[4][4];
        #pragma unroll
        for (int nt = 0; nt < 4; nt++)
            #pragma unroll
            for (int e = 0; e < 4; e++) ex[nt][e] = fast_exp(acc[mt][nt][e]);
        float r0 = 0.f, r1 = 0.f;
        #pragma unroll
        for (int nt = 0; nt < 4; nt++) {
            r0 += ex[nt][0] + ex[nt][1];
            r1 += ex[nt][2] + ex[nt][3];
            csl[nt][0] += ex[nt][0] + ex[nt][2];
            csl[nt][1] += ex[nt][1] + ex[nt][3];
        }
        r0 += __shfl_xor_sync(0xffffffffu, r0, 1);
        r0 += __shfl_xor_sync(0xffffffffu, r0, 2);
        r1 += __shfl_xor_sync(0xffffffffu, r1, 1);
        r1 += __shfl_xor_sync(0xffffffffu, r1, 2);
        int lrow0 = wm*64 + mt*16 + qr;
        if (qc == 0) {
            int rslot = blockIdx.x * 4 + wn;
            g_rpart[((size_t)(z*CS + m0 + lrow0) << 6) + rslot]     = r0;
            g_rpart[((size_t)(z*CS + m0 + lrow0 + 8) << 6) + rslot] = r1;
        }
        #pragma unroll
        for (int nt = 0; nt < 4; nt++) {
            int pc_ = wn*16 + nt*4 + qc;
            Pt[lrow0*PTS + pc_]       = pack_h2(ex[nt][0]*ex[nt][0]*PSCALE,
                                                ex[nt][1]*ex[nt][1]*PSCALE);
            Pt[(lrow0 + 8)*PTS + pc_] = pack_h2(ex[nt][2]*ex[nt][2]*PSCALE,
                                                ex[nt][3]*ex[nt][3]*PSCALE);
        }
    }
    #pragma unroll
    for (int nt = 0; nt < 4; nt++) {
        #pragma unroll
        for (int j = 0; j < 2; j++) {
            float v = csl[nt][j];
            v += __shfl_xor_sync(0xffffffffu, v, 4);
            v += __shfl_xor_sync(0xffffffffu, v, 8);
            v += __shfl_xor_sync(0xffffffffu, v, 16);
            if (qr == 0) {
                int cslot = blockIdx.y * 2 + wm;
                int col = n0 + wn*32 + nt*8 + qc*2 + j;
                g_cpart[((size_t)(z*CS + col) << 5) + cslot] = v;
            }
        }
    }
    __syncthreads();
    #pragma unroll
    for (int i = 0; i < 8; i++) {
        int idx = tid + i*256;
        int row = idx >> 4, c4 = (idx & 15) * 4;
        uint4 v = *(uint4*)&Pt[row*PTS + c4];
        *(uint4*)(g_p + (size_t)(z*CS + m0 + row)*CSP + (n0 >> 1) + c4) = v;
    }
}

// ---------------- finalize ----------------
__global__ __launch_bounds__(256)
void finalize_kernel()
{
    int i = blockIdx.x * 256 + threadIdx.x;
    if (i < CBH*CS) {
        const float4* p = (const float4*)(g_rpart + ((size_t)i << 6));
        float s = 0.f;
        #pragma unroll
        for (int j = 0; j < 16; j++) {
            float4 v = p[j];
            s += v.x + v.y + v.z + v.w;
        }
        g_rsum[i] = 1.0f / s;
    } else {
        i -= CBH*CS;
        const float4* p = (const float4*)(g_cpart + ((size_t)i << 5));
        float s = 0.f;
        #pragma unroll
        for (int j = 0; j < 8; j++) {
            float4 v = p[j];
            s += v.x + v.y + v.z + v.w;
        }
        g_csum[i] = 1.0f / s;
    }
}

// ---------------- V transpose: ci*256 folded, single fp16 -------------------
__global__ __launch_bounds__(256)
void vtrans_ci()
{
    __shared__ float tile[64][65];
    int z = blockIdx.y, b = z >> 3, h = z & 7;
    int t0 = blockIdx.x * 64;
    const float* src = g_v + (size_t)b*CS*CD + h*CDK;
    int tid = threadIdx.x;
    #pragma unroll
    for (int i = 0; i < 16; i++) {
        int idx = tid + i*256;
        int tr = idx >> 6, d = idx & 63;
        tile[tr][d] = src[(size_t)(t0 + tr)*CD + d] * (g_csum[z*CS + t0 + tr] * VSCALE);
    }
    __syncthreads();
    #pragma unroll
    for (int i = 0; i < 8; i++) {
        int idx = tid + i*256;
        int d = idx >> 5, tp = idx & 31;
        g_vt1[((size_t)z*CDK + d)*CSP + (t0 >> 1) + tp] =
            pack_h2(tile[2*tp][d], tile[2*tp+1][d]);
    }
}

// ---------------- PV: fp16 P x fp16 V, fp16 out -----------------------------
__global__ __launch_bounds__(256)
void pv_kernel()
{
    __shared__ uint32_t Ph[2][128][RS];
    __shared__ uint32_t Vh[2][64][RS];
    int z = blockIdx.y, b = z >> 3, h = z & 7;
    int s0 = blockIdx.x * 128;
    int tid = threadIdx.x, wid = tid >> 5, lane = tid & 31;
    int wm = wid & 3, wn = wid >> 2;
    int qr = lane >> 2, qc = lane & 3;

    int pr = tid >> 1;
    int pp = (tid & 1) * 4;
    int vr = tid >> 2;
    int vp = (tid & 3) * 2;
    const uint32_t* aph = g_p   + (size_t)(z*CS + s0 + pr)*CSP;
    const uint32_t* avh = g_vt1 + ((size_t)z*CDK + vr)*CSP;

    const uint32_t BUFP = 128*RS*4, BUFV = 64*RS*4;
    uint32_t aPh = s2u(Ph), aVh = s2u(Vh);
    uint32_t offA = (uint32_t)(lane & 15) * (RS*4) + (uint32_t)((lane >> 4) & 1) * 16;
    uint32_t offB = (uint32_t)((lane & 7) + ((lane >> 4) & 1) * 8) * (RS*4)
                  + (uint32_t)((lane >> 3) & 1) * 16;

    float acc[2][4][4];
    #pragma unroll
    for (int i = 0; i < 2; i++)
        #pragma unroll
        for (int j = 0; j < 4; j++)
            #pragma unroll
            for (int e = 0; e < 4; e++) acc[i][j][e] = 0.f;

    uint4 rp0; uint2 rv0;
    #define PLOAD(c) do { \
        rp0 = *(const uint4*)(aph + (size_t)(c)*8 + pp); \
        rv0 = *(const uint2*)(avh + (size_t)(c)*8 + vp); \
    } while (0)
    #define PSTAGE(bi) do { \
        *(uint4*)&Ph[bi][pr][pp] = rp0; \
        *(uint2*)&Vh[bi][vr][vp] = rv0; \
    } while (0)

    const int NC = CS / 16;            // 128 chunks
    PLOAD(0); PSTAGE(0); PLOAD(1);
    __syncthreads();

    for (int c = 0; c < NC; c++) {
        uint32_t cbP = (uint32_t)(c & 1) * BUFP;
        uint32_t cbV = (uint32_t)(c & 1) * BUFV;
        uint32_t bh[4][2];
        #pragma unroll
        for (int ntp = 0; ntp < 2; ntp++) {
            uint32_t nbase = (uint32_t)(wn*32 + ntp*16) * (RS*4);
            ldsm4(bh[2*ntp][0], bh[2*ntp][1], bh[2*ntp+1][0], bh[2*ntp+1][1], aVh + cbV + nbase + offB);
        }
        #pragma unroll
        for (int mt = 0; mt < 2; mt++) {
            uint32_t rbase = (uint32_t)(wm*32 + mt*16) * (RS*4);
            uint32_t a0, a1, a2, a3;
            ldsm4(a0, a1, a2, a3, aPh + cbP + rbase + offA);
            #pragma unroll
            for (int nt = 0; nt < 4; nt++)
                mma16h(acc[mt][nt][0], acc[mt][nt][1], acc[mt][nt][2], acc[mt][nt][3],
                       a0, a1, a2, a3, bh[nt][0], bh[nt][1]);
        }
        if (c + 1 < NC) {
            PSTAGE((c+1) & 1);
            if (c + 2 < NC) PLOAD(c+2);
        }
        __syncthreads();
    }
    #undef PLOAD
    #undef PSTAGE
    #pragma unroll
    for (int mt = 0; mt < 2; mt++) {
        #pragma unroll
        for (int half = 0; half < 2; half++) {
            int srow = s0 + wm*32 + mt*16 + qr + half*8;
            float ri = g_rsum[(size_t)z*CS + srow];
            const float* grow = g_gate + ((size_t)b*CS + srow)*CD + h*CDK;
            uint32_t* orow    = g_aop1 + ((size_t)b*CS + srow)*CDP + h*32;
            #pragma unroll
            for (int nt = 0; nt < 4; nt++) {
                int col = wn*32 + nt*8 + qc*2;
                float2 gg = *(const float2*)(grow + col);
                float o0 = acc[mt][nt][half*2+0] * ri * gg.x;
                float o1 = acc[mt][nt][half*2+1] * ri * gg.y;
                orow[col >> 1] = pack_h2(o0, o1);
            }
        }
    }
}

// ---------------- output projection: fp16 A single x fp16 Wo split ----------
__global__ __launch_bounds__(256, 2)
void out_gemm(const float* __restrict__ bo, float* __restrict__ C)
{
    __shared__ uint32_t Ah[2][128][RS];
    __shared__ uint32_t Bh[2][128][RS], Bl[2][128][RS];
    int tid = threadIdx.x, wid = tid >> 5, lane = tid & 31;
    int wm = wid & 1, wn = wid >> 1;
    int m0 = blockIdx.y * 128, n0 = blockIdx.x * 128;
    const uint32_t* Ag = g_aop1 + (size_t)m0 * CDP;
    const uint2*    Bg = g_wp[4] + (size_t)n0 * CDP;
    int lr = tid >> 2, kp = (tid & 3) * 2;
    int qr = lane >> 2, qc = lane & 3;

    const uint32_t BUF = 128*RS*4;
    uint32_t aAh = s2u(Ah), aBh = s2u(Bh), aBl = s2u(Bl);
    uint32_t offA = (uint32_t)(lane & 15) * (RS*4) + (uint32_t)((lane >> 4) & 1) * 16;
    uint32_t offB = (uint32_t)((lane & 7) + ((lane >> 4) & 1) * 8) * (RS*4)
                  + (uint32_t)((lane >> 3) & 1) * 16;

    float acc[4][4][4];
    #pragma unroll
    for (int i = 0; i < 4; i++)
        #pragma unroll
        for (int j = 0; j < 4; j++)
            #pragma unroll
            for (int e = 0; e < 4; e++) acc[i][j][e] = 0.f;

    uint2 rA0, rA1; uint4 rB0, rB1;
    #define OLOAD(c) do { \
        size_t o0_ = (size_t)lr*CDP + (size_t)(c)*8 + kp; \
        size_t o1_ = (size_t)(lr+64)*CDP + (size_t)(c)*8 + kp; \
        rA0 = *(const uint2*)(Ag + o0_); rA1 = *(const uint2*)(Ag + o1_); \
        rB0 = *(const uint4*)(Bg + o0_); rB1 = *(const uint4*)(Bg + o1_); \
    } while (0)
    #define OSTAGE(bi) do { \
        *(uint2*)&Ah[bi][lr][kp]    = rA0; \
        *(uint2*)&Ah[bi][lr+64][kp] = rA1; \
        *(uint2*)&Bh[bi][lr][kp]    = make_uint2(rB0.x, rB0.z); \
        *(uint2*)&Bl[bi][lr][kp]    = make_uint2(rB0.y, rB0.w); \
        *(uint2*)&Bh[bi][lr+64][kp] = make_uint2(rB1.x, rB1.z); \
        *(uint2*)&Bl[bi][lr+64][kp] = make_uint2(rB1.y, rB1.w); \
    } while (0)

    const int NC = CD / 16;
    OLOAD(0); OSTAGE(0); OLOAD(1);
    __syncthreads();

    for (int c = 0; c < NC; c++) {
        uint32_t cb = (uint32_t)(c & 1) * BUF;
        uint32_t bh[4][2], bl[4][2];
        #pragma unroll
        for (int ntp = 0; ntp < 2; ntp++) {
            uint32_t nbase = (uint32_t)(wn*32 + ntp*16) * (RS*4);
            ldsm4(bh[2*ntp][0], bh[2*ntp][1], bh[2*ntp+1][0], bh[2*ntp+1][1], aBh + cb + nbase + offB);
            ldsm4(bl[2*ntp][0], bl[2*ntp][1], bl[2*ntp+1][0], bl[2*ntp+1][1], aBl + cb + nbase + offB);
        }
        #pragma unroll
        for (int mt = 0; mt < 4; mt++) {
            uint32_t rbase = (uint32_t)(wm*64 + mt*16) * (RS*4);
            uint32_t a0, a1, a2, a3;
            ldsm4(a0, a1, a2, a3, aAh + cb + rbase + offA);
            #pragma unroll
            for (int nt = 0; nt < 4; nt++) {
                mma16h(acc[mt][nt][0], acc[mt][nt][1], acc[mt][nt][2], acc[mt][nt][3],
                       a0, a1, a2, a3, bh[nt][0], bh[nt][1]);
                mma16h(acc[mt][nt][0], acc[mt][nt][1], acc[mt][nt][2], acc[mt][nt][3],
                       a0, a1, a2, a3, bl[nt][0], bl[nt][1]);
            }
        }
        if (c + 1 < NC) {
            OSTAGE((c+1) & 1);
            if (c + 2 < NC) OLOAD(c+2);
        }
        __syncthreads();
    }
    #undef OLOAD
    #undef OSTAGE
    #pragma unroll
    for (int mt = 0; mt < 4; mt++) {
        int r = m0 + wm*64 + mt*16 + qr;
        #pragma unroll
        for (int nt = 0; nt < 4; nt++) {
            int col = n0 + wn*32 + nt*8 + qc*2;
            float b0 = bo[col], b1 = bo[col+1];
            *(float2*)(C + (size_t)r*CD + col) =
                make_float2(acc[mt][nt][0] + b0, acc[mt][nt][1] + b1);
            *(float2*)(C + (size_t)(r+8)*CD + col) =
                make_float2(acc[mt][nt][2] + b0, acc[mt][nt][3] + b1);
        }
    }
}

// ---------------- launch ----------------
extern "C" void kernel_launch(void* const* d_in, const int* in_sizes, int n_in,
                              void* d_out, int out_size)
{
    const float* x_q   = (const float*)d_in[0];
    const float* x_k   = (const float*)d_in[1];
    const float* Wq    = (const float*)d_in[2];
    const float* Wk    = (const float*)d_in[3];
    const float* Wv    = (const float*)d_in[4];
    const float* Wg    = (const float*)d_in[5];
    const float* bg    = (const float*)d_in[6];
    const float* Wo    = (const float*)d_in[7];
    const float* bo    = (const float*)d_in[8];
    const float* gamma = (const float*)d_in[9];
    const float* beta  = (const float*)d_in[10];
    float* out = (float*)d_out;

    const int SM_SCORES = 12*128*RS*4;   // 72KB
    cudaFuncSetAttribute(scores_stats,
                         cudaFuncAttributeMaxDynamicSharedMemorySize, SM_SCORES);

    // 1. LayerNorm (fp16 split) + weight split (fp16)
    ln_kernel<<<2*CM, 256>>>(x_q, x_k, gamma, beta);
    wsplit_kernel<<<dim3(CD*CDP/256, 5), 256>>>(Wq, Wk, Wv, Wg, Wo);

    // 2. All projections (q,k 3-MMA; v,gate 2-MMA)
    proj_all<<<dim3(CD/128, CM/128, 4), 256>>>(bg);

    // 3. Scores + stats: q-split x k-single, 2 MMAs, coalesced P stores
    scores_stats<<<dim3(CS/128, CS/128, CBH), 256, SM_SCORES>>>();

    // 4. Reduce partials -> reciprocal sums
    finalize_kernel<<<(2*CBH*CS)/256, 256>>>();

    // 5. V transpose with ci*256 folded, single fp16
    vtrans_ci<<<dim3(CS/64, CBH), 256>>>();

    // 6. PV: single fp16 MMA per tile, fp16 out
    pv_kernel<<<dim3(CS/128, CBH), 256>>>();

    // 7. Output projection + bias -> d_out
    out_gemm<<<dim3(CD/128, CM/128), 256>>>(bo, out);
}

// round 17
// speedup vs baseline: 1.6644x; 1.0664x over previous
#include <cuda_runtime.h>
#include <cuda_bf16.h>
#include <cuda_fp16.h>
#include <cstdint>
#include <math.h>

#define CB 4
#define CS 2048
#define CD 512
#define CH 8
#define CDK 64
#define CM (CB*CS)      // 8192
#define CBH (CB*CH)     // 32
#define CDP (CD/2)      // 256 pairs per D row
#define CSP (CS/2)      // 1024 pairs per score row

typedef unsigned long long u64;

// ---------------- scratch (device globals: allocation-free) ----------------
static __device__ uint2 g_xqp[CM*CDP];                // LN(xq) fp16 split
static __device__ uint2 g_xkp[CM*CDP];                // LN(xk) fp16 split
static __device__ uint2 g_wp[5][CD*CDP];              // weights fp16 split
static __device__ uint2 g_qp[CM*CDP];                 // q/8 fp16 split
static __device__ uint32_t g_kp1[CM*CDP];             // k single fp16 pairs
static __device__ float g_v[CM*CD];
static __device__ float g_gate[CM*CD];
static __device__ uint32_t g_aop1[CM*CDP];            // attn-out*ri*gate fp16 pairs
static __device__ uint32_t g_p[(size_t)CBH*CS*CSP];   // fp16x2: exp(2x)*2^-8
static __device__ uint32_t g_vt1[CBH*CDK*CSP];        // fp16x2: V^T*csum
static __device__ float g_rpart[(size_t)CBH*CS*64];   // partials of sum(exp(x)*2^-4)
static __device__ float g_cpart[(size_t)CBH*CS*32];
static __device__ float g_rsum[CBH*CS];               // 16/sum(exp) -- cancels P's 2^-8
static __device__ float g_csum[CBH*CS];
// scale algebra: P = exp(2x)*2^-8; rsum,csum = 1/(sum exp * 2^-4);
// out = P*Vt*ri = e^2*2^-8 * v*(16/Sc) * (16/Sr) = e^2 v/(Sr*Sc)  (exact)

// ---------------- helpers ----------------
__device__ __forceinline__ uint32_t s2u(const void* p) {
    return (uint32_t)__cvta_generic_to_shared(p);
}
__device__ __forceinline__ uint32_t pack_h2(float x0, float x1) {
    __half2 h = __floats2half2_rn(x0, x1);
    return *(uint32_t*)&h;
}
__device__ __forceinline__ void splith2(float x0, float x1, uint32_t &hi, uint32_t &lo) {
    __half h0 = __float2half_rn(x0);
    __half h1 = __float2half_rn(x1);
    float r0 = x0 - __half2float(h0);
    float r1 = x1 - __half2float(h1);
    __half l0 = __float2half_rn(r0);
    __half l1 = __float2half_rn(r1);
    hi = (uint32_t)__half_as_ushort(h0) | ((uint32_t)__half_as_ushort(h1) << 16);
    lo = (uint32_t)__half_as_ushort(l0) | ((uint32_t)__half_as_ushort(l1) << 16);
}
__device__ __forceinline__ void mma16h(float &c0, float &c1, float &c2, float &c3,
                                       uint32_t a0, uint32_t a1, uint32_t a2, uint32_t a3,
                                       uint32_t b0, uint32_t b1) {
    asm("mma.sync.aligned.m16n8k16.row.col.f32.f16.f16.f32 "
        "{%0,%1,%2,%3}, {%4,%5,%6,%7}, {%8,%9}, {%0,%1,%2,%3};"
        : "+f"(c0), "+f"(c1), "+f"(c2), "+f"(c3)
        : "r"(a0), "r"(a1), "r"(a2), "r"(a3), "r"(b0), "r"(b1));
}
__device__ __forceinline__ void ldsm4(uint32_t &r0, uint32_t &r1, uint32_t &r2, uint32_t &r3,
                                      uint32_t addr) {
    asm volatile("ldmatrix.sync.aligned.m8n8.x4.shared.b16 {%0,%1,%2,%3}, [%4];"
                 : "=r"(r0), "=r"(r1), "=r"(r2), "=r"(r3) : "r"(addr));
}
#define RS 12   // SMEM row stride in uint32 (48B, conflict-free)

// ---------------- packed f32x2 helpers ----------------
__device__ __forceinline__ u64 dup2f(float x) {
    u64 r; asm("mov.b64 %0,{%1,%1};" : "=l"(r) : "f"(x)); return r;
}
__device__ __forceinline__ u64 pk2f(float a, float b) {
    u64 r; asm("mov.b64 %0,{%1,%2};" : "=l"(r) : "f"(a), "f"(b)); return r;
}
__device__ __forceinline__ void upk2f(u64 v, float &a, float &b) {
    asm("mov.b64 {%0,%1},%2;" : "=f"(a), "=f"(b) : "l"(v));
}
__device__ __forceinline__ u64 add2v(u64 a, u64 b) {
    u64 r; asm("add.rn.f32x2 %0,%1,%2;" : "=l"(r) : "l"(a), "l"(b)); return r;
}
__device__ __forceinline__ u64 mul2v(u64 a, u64 b) {
    u64 r; asm("mul.rn.f32x2 %0,%1,%2;" : "=l"(r) : "l"(a), "l"(b)); return r;
}
__device__ __forceinline__ u64 fma2v(u64 a, u64 b, u64 c) {
    u64 r; asm("fma.rn.f32x2 %0,%1,%2,%3;" : "=l"(r) : "l"(a), "l"(b), "l"(c)); return r;
}
// packed exp(x) * 2^-4 for two lanes (magic-RN + deg-5 Taylor, scale folded)
__device__ __forceinline__ u64 exp2k(u64 x2) {
    u64 t  = mul2v(x2, dup2f(1.4426950408889634f));
    u64 rm = add2v(t, dup2f(12582912.0f));            // 1.5*2^23, RN
    u64 nf = add2v(rm, dup2f(-12582912.0f));          // exact n as float
    u64 f  = fma2v(nf, dup2f(-1.0f), t);              // f = t - n in [-0.5,0.5]
    u64 u  = mul2v(f, dup2f(0.6931471805599453f));
    u64 p  = dup2f(0.008333334f);
    p = fma2v(p, u, dup2f(0.041666668f));
    p = fma2v(p, u, dup2f(0.16666667f));
    p = fma2v(p, u, dup2f(0.5f));
    p = fma2v(p, u, dup2f(1.0f));
    p = fma2v(p, u, dup2f(1.0f));
    uint32_t blo, bhi;
    asm("mov.b64 {%0,%1},%2;" : "=r"(blo), "=r"(bhi) : "l"(rm));
    blo = (blo + 0xB4C0007Bu) << 23;                  // 2^(n+123-127) = 2^n * 2^-4
    bhi = (bhi + 0xB4C0007Bu) << 23;
    u64 sc; asm("mov.b64 %0,{%1,%2};" : "=l"(sc) : "r"(blo), "r"(bhi));
    return mul2v(p, sc);
}

// ---------------- LayerNorm -> fp16 split ----------------
__global__ __launch_bounds__(256)
void ln_kernel(const float* __restrict__ xq, const float* __restrict__ xk,
               const float* __restrict__ gamma, const float* __restrict__ beta)
{
    int row = blockIdx.x;
    const float* x; uint2* o;
    if (row < CM) { x = xq + (size_t)row*CD;       o = g_xqp + (size_t)row*CDP; }
    else          { x = xk + (size_t)(row-CM)*CD;  o = g_xkp + (size_t)(row-CM)*CDP; }
    int t = threadIdx.x;
    float2 v2 = ((const float2*)x)[t];
    float s  = v2.x + v2.y;
    float ss = v2.x*v2.x + v2.y*v2.y;
    #pragma unroll
    for (int off = 16; off; off >>= 1) {
        s  += __shfl_xor_sync(0xffffffffu, s,  off);
        ss += __shfl_xor_sync(0xffffffffu, ss, off);
    }
    __shared__ float sh_s[8], sh_ss[8];
    __shared__ float s_mean, s_rstd;
    int wid = t >> 5, lid = t & 31;
    if (lid == 0) { sh_s[wid] = s; sh_ss[wid] = ss; }
    __syncthreads();
    if (t < 32) {
        float a = (t < 8) ? sh_s[t]  : 0.f;
        float b = (t < 8) ? sh_ss[t] : 0.f;
        #pragma unroll
        for (int off = 4; off; off >>= 1) {
            a += __shfl_xor_sync(0xffffffffu, a, off);
            b += __shfl_xor_sync(0xffffffffu, b, off);
        }
        if (t == 0) {
            float mean = a * (1.0f/CD);
            float var  = b * (1.0f/CD) - mean*mean;
            s_mean = mean;
            s_rstd = rsqrtf(var + 1e-6f);
        }
    }
    __syncthreads();
    float mean = s_mean, rstd = s_rstd;
    float2 g2 = ((const float2*)gamma)[t];
    float2 b2 = ((const float2*)beta)[t];
    float o0 = (v2.x - mean) * rstd * g2.x + b2.x;
    float o1 = (v2.y - mean) * rstd * g2.y + b2.y;
    uint2 pk;
    splith2(o0, o1, pk.x, pk.y);
    o[t] = pk;
}

// ---------------- weight split: all fp16 ----------------
__global__ __launch_bounds__(256)
void wsplit_kernel(const float* __restrict__ Wq, const float* __restrict__ Wk,
                   const float* __restrict__ Wv, const float* __restrict__ Wg,
                   const float* __restrict__ Wo)
{
    int m = blockIdx.y;
    const float* W = (m == 0) ? Wq : (m == 1) ? Wk : (m == 2) ? Wv : (m == 3) ? Wg : Wo;
    int idx = blockIdx.x * 256 + threadIdx.x;
    float2 v = ((const float2*)W)[idx];
    uint2 pk;
    splith2(v.x, v.y, pk.x, pk.y);
    g_wp[m][idx] = pk;
}

// ---------------- merged projections (fp16) ---------------------------------
__global__ __launch_bounds__(256, 2)
void proj_all(const float* __restrict__ bg)
{
    __shared__ uint32_t Ah[2][128][RS], Al[2][128][RS];
    __shared__ uint32_t Bh[2][128][RS], Bl[2][128][RS];
    int mode = blockIdx.z;
    bool fullB = (mode <= 1);
    const uint2* A = (mode == 0 || mode == 3) ? g_xqp : g_xkp;
    const uint2* B = g_wp[mode];
    float scale = (mode == 0) ? 0.125f : 1.0f;

    int tid = threadIdx.x, wid = tid >> 5, lane = tid & 31;
    int wm = wid & 1, wn = wid >> 1;
    int m0 = blockIdx.y * 128, n0 = blockIdx.x * 128;
    const uint2* Ag = A + (size_t)m0 * CDP;
    const uint2* Bg = B + (size_t)n0 * CDP;
    int lr = tid >> 2, kp = (tid & 3) * 2;
    int qr = lane >> 2, qc = lane & 3;

    const uint32_t BUF = 128*RS*4;
    uint32_t aAh = s2u(Ah), aAl = s2u(Al), aBh = s2u(Bh), aBl = s2u(Bl);
    uint32_t offA = (uint32_t)(lane & 15) * (RS*4) + (uint32_t)((lane >> 4) & 1) * 16;
    uint32_t offB = (uint32_t)((lane & 7) + ((lane >> 4) & 1) * 8) * (RS*4)
                  + (uint32_t)((lane >> 3) & 1) * 16;

    float acc[4][4][4];
    #pragma unroll
    for (int i = 0; i < 4; i++)
        #pragma unroll
        for (int j = 0; j < 4; j++)
            #pragma unroll
            for (int e = 0; e < 4; e++) acc[i][j][e] = 0.f;

    uint4 rA0, rA1, rB0, rB1;
    #define GLOAD(c) do { \
        size_t o0_ = (size_t)lr*CDP + (size_t)(c)*8 + kp; \
        size_t o1_ = (size_t)(lr+64)*CDP + (size_t)(c)*8 + kp; \
        rA0 = *(const uint4*)(Ag + o0_); rA1 = *(const uint4*)(Ag + o1_); \
        rB0 = *(const uint4*)(Bg + o0_); rB1 = *(const uint4*)(Bg + o1_); \
    } while (0)
    #define GSTAGE(bi) do { \
        *(uint2*)&Ah[bi][lr][kp]    = make_uint2(rA0.x, rA0.z); \
        *(uint2*)&Al[bi][lr][kp]    = make_uint2(rA0.y, rA0.w); \
        *(uint2*)&Ah[bi][lr+64][kp] = make_uint2(rA1.x, rA1.z); \
        *(uint2*)&Al[bi][lr+64][kp] = make_uint2(rA1.y, rA1.w); \
        *(uint2*)&Bh[bi][lr][kp]    = make_uint2(rB0.x, rB0.z); \
        *(uint2*)&Bh[bi][lr+64][kp] = make_uint2(rB1.x, rB1.z); \
        if (fullB) { \
            *(uint2*)&Bl[bi][lr][kp]    = make_uint2(rB0.y, rB0.w); \
            *(uint2*)&Bl[bi][lr+64][kp] = make_uint2(rB1.y, rB1.w); \
        } \
    } while (0)

    const int NC = CD / 16;    // 32
    GLOAD(0); GSTAGE(0); GLOAD(1);
    __syncthreads();

    for (int c = 0; c < NC; c++) {
        uint32_t cb = (uint32_t)(c & 1) * BUF;
        uint32_t bh[4][2], bl[4][2];
        #pragma unroll
        for (int ntp = 0; ntp < 2; ntp++) {
            uint32_t nbase = (uint32_t)(wn*32 + ntp*16) * (RS*4);
            ldsm4(bh[2*ntp][0], bh[2*ntp][1], bh[2*ntp+1][0], bh[2*ntp+1][1], aBh + cb + nbase + offB);
            if (fullB)
                ldsm4(bl[2*ntp][0], bl[2*ntp][1], bl[2*ntp+1][0], bl[2*ntp+1][1], aBl + cb + nbase + offB);
        }
        #pragma unroll
        for (int mt = 0; mt < 4; mt++) {
            uint32_t rbase = (uint32_t)(wm*64 + mt*16) * (RS*4);
            uint32_t ah0, ah1, ah2, ah3, al0, al1, al2, al3;
            ldsm4(ah0, ah1, ah2, ah3, aAh + cb + rbase + offA);
            ldsm4(al0, al1, al2, al3, aAl + cb + rbase + offA);
            #pragma unroll
            for (int nt = 0; nt < 4; nt++) {
                mma16h(acc[mt][nt][0], acc[mt][nt][1], acc[mt][nt][2], acc[mt][nt][3],
                       ah0, ah1, ah2, ah3, bh[nt][0], bh[nt][1]);
                mma16h(acc[mt][nt][0], acc[mt][nt][1], acc[mt][nt][2], acc[mt][nt][3],
                       al0, al1, al2, al3, bh[nt][0], bh[nt][1]);
                if (fullB)
                    mma16h(acc[mt][nt][0], acc[mt][nt][1], acc[mt][nt][2], acc[mt][nt][3],
                           ah0, ah1, ah2, ah3, bl[nt][0], bl[nt][1]);
            }
        }
        if (c + 1 < NC) {
            GSTAGE((c+1) & 1);
            if (c + 2 < NC) GLOAD(c+2);
        }
        __syncthreads();
    }
    #undef GLOAD
    #undef GSTAGE

    if (mode == 0) {
        #pragma unroll
        for (int mt = 0; mt < 4; mt++) {
            int r = m0 + wm*64 + mt*16 + qr;
            #pragma unroll
            for (int nt = 0; nt < 4; nt++) {
                int colp = (n0 >> 1) + wn*16 + nt*4 + qc;
                uint2 pk;
                splith2(acc[mt][nt][0]*scale, acc[mt][nt][1]*scale, pk.x, pk.y);
                g_qp[(size_t)r*CDP + colp] = pk;
                splith2(acc[mt][nt][2]*scale, acc[mt][nt][3]*scale, pk.x, pk.y);
                g_qp[(size_t)(r+8)*CDP + colp] = pk;
            }
        }
    } else if (mode == 1) {
        #pragma unroll
        for (int mt = 0; mt < 4; mt++) {
            int r = m0 + wm*64 + mt*16 + qr;
            #pragma unroll
            for (int nt = 0; nt < 4; nt++) {
                int colp = (n0 >> 1) + wn*16 + nt*4 + qc;
                g_kp1[(size_t)r*CDP + colp]     = pack_h2(acc[mt][nt][0], acc[mt][nt][1]);
                g_kp1[(size_t)(r+8)*CDP + colp] = pack_h2(acc[mt][nt][2], acc[mt][nt][3]);
            }
        }
    } else {
        float* O = (mode == 2) ? g_v : g_gate;
        #pragma unroll
        for (int mt = 0; mt < 4; mt++) {
            int r = m0 + wm*64 + mt*16 + qr;
            #pragma unroll
            for (int nt = 0; nt < 4; nt++) {
                int col = n0 + wn*32 + nt*8 + qc*2;
                float o0 = acc[mt][nt][0], o1 = acc[mt][nt][1];
                float o2 = acc[mt][nt][2], o3 = acc[mt][nt][3];
                if (mode == 3) {
                    float b0 = bg[col], b1 = bg[col+1];
                    o0 = 1.0f/(1.0f + __expf(-(o0+b0)));
                    o1 = 1.0f/(1.0f + __expf(-(o1+b1)));
                    o2 = 1.0f/(1.0f + __expf(-(o2+b0)));
                    o3 = 1.0f/(1.0f + __expf(-(o3+b1)));
                }
                *(float2*)(O + (size_t)r*CD + col)     = make_float2(o0, o1);
                *(float2*)(O + (size_t)(r+8)*CD + col) = make_float2(o2, o3);
            }
        }
    }
}

// ---------------- scores + stats: packed-f32x2 exp epilogue -----------------
#define PTS 68   // P-tile row stride in uint32
__global__ __launch_bounds__(256, 2)
void scores_stats()
{
    extern __shared__ uint32_t SM[];   // 72KB: Ah,Al,Bh x4 chunks; then P-tile
    const uint32_t BUF = 128*RS*4;
    uint32_t aAh = s2u(SM);
    uint32_t aAl = aAh + 4*BUF;
    uint32_t aBh = aAh + 8*BUF;
    int z = blockIdx.z, b = z >> 3, h = z & 7;
    int m0 = blockIdx.y * 128, n0 = blockIdx.x * 128;
    int tid = threadIdx.x, wid = tid >> 5, lane = tid & 31;
    int wm = wid & 1, wn = wid >> 1;
    int lr = tid >> 2, kp = (tid & 3) * 2;
    int qr = lane >> 2, qc = lane & 3;

    const uint2*    Ag = g_qp  + (size_t)(b*CS + m0)*CDP + h*32;
    const uint32_t* Bg = g_kp1 + (size_t)(b*CS + n0)*CDP + h*32;

    uint32_t offA = (uint32_t)(lane & 15) * (RS*4) + (uint32_t)((lane >> 4) & 1) * 16;
    uint32_t offB = (uint32_t)((lane & 7) + ((lane >> 4) & 1) * 8) * (RS*4)
                  + (uint32_t)((lane >> 3) & 1) * 16;

    float acc[4][4][4];
    #pragma unroll
    for (int i = 0; i < 4; i++)
        #pragma unroll
        for (int j = 0; j < 4; j++)
            #pragma unroll
            for (int e = 0; e < 4; e++) acc[i][j][e] = 0.f;

    #define SSTORE(addr, v2_) asm volatile("st.shared.v2.u32 [%0], {%1,%2};" \
        :: "r"(addr), "r"((v2_).x), "r"((v2_).y) : "memory")
    #pragma unroll
    for (int c = 0; c < 4; c++) {
        size_t o0_ = (size_t)lr*CDP + (size_t)c*8 + kp;
        size_t o1_ = (size_t)(lr+64)*CDP + (size_t)c*8 + kp;
        uint4 rA0 = *(const uint4*)(Ag + o0_), rA1 = *(const uint4*)(Ag + o1_);
        uint2 rB0 = *(const uint2*)(Bg + o0_), rB1 = *(const uint2*)(Bg + o1_);
        uint32_t rowb  = (uint32_t)lr*(RS*4) + (uint32_t)kp*4 + (uint32_t)c*BUF;
        uint32_t rowb2 = rowb + 64*(RS*4);
        SSTORE(aAh + rowb,  make_uint2(rA0.x, rA0.z));
        SSTORE(aAl + rowb,  make_uint2(rA0.y, rA0.w));
        SSTORE(aAh + rowb2, make_uint2(rA1.x, rA1.z));
        SSTORE(aAl + rowb2, make_uint2(rA1.y, rA1.w));
        SSTORE(aBh + rowb,  rB0);
        SSTORE(aBh + rowb2, rB1);
    }
    #undef SSTORE
    __syncthreads();

    #pragma unroll
    for (int c = 0; c < 4; c++) {
        uint32_t cb = (uint32_t)c * BUF;
        uint32_t bh[4][2];
        #pragma unroll
        for (int ntp = 0; ntp < 2; ntp++) {
            uint32_t nbase = (uint32_t)(wn*32 + ntp*16) * (RS*4);
            ldsm4(bh[2*ntp][0], bh[2*ntp][1], bh[2*ntp+1][0], bh[2*ntp+1][1], aBh + cb + nbase + offB);
        }
        #pragma unroll
        for (int mt = 0; mt < 4; mt++) {
            uint32_t rbase = (uint32_t)(wm*64 + mt*16) * (RS*4);
            uint32_t ah0, ah1, ah2, ah3, al0, al1, al2, al3;
            ldsm4(ah0, ah1, ah2, ah3, aAh + cb + rbase + offA);
            ldsm4(al0, al1, al2, al3, aAl + cb + rbase + offA);
            #pragma unroll
            for (int nt = 0; nt < 4; nt++) {
                mma16h(acc[mt][nt][0], acc[mt][nt][1], acc[mt][nt][2], acc[mt][nt][3],
                       ah0, ah1, ah2, ah3, bh[nt][0], bh[nt][1]);
                mma16h(acc[mt][nt][0], acc[mt][nt][1], acc[mt][nt][2], acc[mt][nt][3],
                       al0, al1, al2, al3, bh[nt][0], bh[nt][1]);
            }
        }
    }
    __syncthreads();   // staging dead; P-tile reuse

    uint32_t* Pt = SM;   // [128][PTS]
    u64 cp[4];
    #pragma unroll
    for (int nt = 0; nt < 4; nt++) cp[nt] = 0ull;   // packed (0,0)
    #pragma unroll
    for (int mt = 0; mt < 4; mt++) {
        u64 e01[4], e23[4];
        #pragma unroll
        for (int nt = 0; nt < 4; nt++) {
            e01[nt] = exp2k(pk2f(acc[mt][nt][0], acc[mt][nt][1]));
            e23[nt] = exp2k(pk2f(acc[mt][nt][2], acc[mt][nt][3]));
        }
        u64 rp01 = 0ull, rp23 = 0ull;
        #pragma unroll
        for (int nt = 0; nt < 4; nt++) {
            rp01 = add2v(rp01, e01[nt]);
            rp23 = add2v(rp23, e23[nt]);
            cp[nt] = add2v(cp[nt], add2v(e01[nt], e23[nt]));
        }
        float ra, rb;
        upk2f(rp01, ra, rb);  float r0 = ra + rb;
        upk2f(rp23, ra, rb);  float r1 = ra + rb;
        r0 += __shfl_xor_sync(0xffffffffu, r0, 1);
        r0 += __shfl_xor_sync(0xffffffffu, r0, 2);
        r1 += __shfl_xor_sync(0xffffffffu, r1, 1);
        r1 += __shfl_xor_sync(0xffffffffu, r1, 2);
        int lrow0 = wm*64 + mt*16 + qr;
        if (qc == 0) {
            int rslot = blockIdx.x * 4 + wn;
            g_rpart[((size_t)(z*CS + m0 + lrow0) << 6) + rslot]     = r0;
            g_rpart[((size_t)(z*CS + m0 + lrow0 + 8) << 6) + rslot] = r1;
        }
        #pragma unroll
        for (int nt = 0; nt < 4; nt++) {
            int pc_ = wn*16 + nt*4 + qc;
            u64 s01 = mul2v(e01[nt], e01[nt]);   // exp(2x)*2^-8
            u64 s23 = mul2v(e23[nt], e23[nt]);
            float a0, a1;
            upk2f(s01, a0, a1);
            Pt[lrow0*PTS + pc_] = pack_h2(a0, a1);
            upk2f(s23, a0, a1);
            Pt[(lrow0 + 8)*PTS + pc_] = pack_h2(a0, a1);
        }
    }
    #pragma unroll
    for (int nt = 0; nt < 4; nt++) {
        float c0, c1;
        upk2f(cp[nt], c0, c1);
        #pragma unroll
        for (int j = 0; j < 2; j++) {
            float v = (j == 0) ? c0 : c1;
            v += __shfl_xor_sync(0xffffffffu, v, 4);
            v += __shfl_xor_sync(0xffffffffu, v, 8);
            v += __shfl_xor_sync(0xffffffffu, v, 16);
            if (qr == 0) {
                int cslot = blockIdx.y * 2 + wm;
                int col = n0 + wn*32 + nt*8 + qc*2 + j;
                g_cpart[((size_t)(z*CS + col) << 5) + cslot] = v;
            }
        }
    }
    __syncthreads();
    #pragma unroll
    for (int i = 0; i < 8; i++) {
        int idx = tid + i*256;
        int row = idx >> 4, c4 = (idx & 15) * 4;
        uint4 v = *(uint4*)&Pt[row*PTS + c4];
        *(uint4*)(g_p + (size_t)(z*CS + m0 + row)*CSP + (n0 >> 1) + c4) = v;
    }
}

// ---------------- finalize ----------------
__global__ __launch_bounds__(256)
void finalize_kernel()
{
    int i = blockIdx.x * 256 + threadIdx.x;
    if (i < CBH*CS) {
        const float4* p = (const float4*)(g_rpart + ((size_t)i << 6));
        float s = 0.f;
        #pragma unroll
        for (int j = 0; j < 16; j++) {
            float4 v = p[j];
            s += v.x + v.y + v.z + v.w;
        }
        g_rsum[i] = 1.0f / s;
    } else {
        i -= CBH*CS;
        const float4* p = (const float4*)(g_cpart + ((size_t)i << 5));
        float s = 0.f;
        #pragma unroll
        for (int j = 0; j < 8; j++) {
            float4 v = p[j];
            s += v.x + v.y + v.z + v.w;
        }
        g_csum[i] = 1.0f / s;
    }
}

// ---------------- V transpose: csum folded, single fp16 ---------------------
__global__ __launch_bounds__(256)
void vtrans_ci()
{
    __shared__ float tile[64][65];
    int z = blockIdx.y, b = z >> 3, h = z & 7;
    int t0 = blockIdx.x * 64;
    const float* src = g_v + (size_t)b*CS*CD + h*CDK;
    int tid = threadIdx.x;
    #pragma unroll
    for (int i = 0; i < 16; i++) {
        int idx = tid + i*256;
        int tr = idx >> 6, d = idx & 63;
        tile[tr][d] = src[(size_t)(t0 + tr)*CD + d] * g_csum[z*CS + t0 + tr];
    }
    __syncthreads();
    #pragma unroll
    for (int i = 0; i < 8; i++) {
        int idx = tid + i*256;
        int d = idx >> 5, tp = idx & 31;
        g_vt1[((size_t)z*CDK + d)*CSP + (t0 >> 1) + tp] =
            pack_h2(tile[2*tp][d], tile[2*tp+1][d]);
    }
}

// ---------------- PV: fp16 P x fp16 V, fp16 out -----------------------------
__global__ __launch_bounds__(256, 3)
void pv_kernel()
{
    __shared__ uint32_t Ph[2][128][RS];
    __shared__ uint32_t Vh[2][64][RS];
    int z = blockIdx.y, b = z >> 3, h = z & 7;
    int s0 = blockIdx.x * 128;
    int tid = threadIdx.x, wid = tid >> 5, lane = tid & 31;
    int wm = wid & 3, wn = wid >> 2;
    int qr = lane >> 2, qc = lane & 3;

    int pr = tid >> 1;
    int pp = (tid & 1) * 4;
    int vr = tid >> 2;
    int vp = (tid & 3) * 2;
    const uint32_t* aph = g_p   + (size_t)(z*CS + s0 + pr)*CSP;
    const uint32_t* avh = g_vt1 + ((size_t)z*CDK + vr)*CSP;

    const uint32_t BUFP = 128*RS*4, BUFV = 64*RS*4;
    uint32_t aPh = s2u(Ph), aVh = s2u(Vh);
    uint32_t offA = (uint32_t)(lane & 15) * (RS*4) + (uint32_t)((lane >> 4) & 1) * 16;
    uint32_t offB = (uint32_t)((lane & 7) + ((lane >> 4) & 1) * 8) * (RS*4)
                  + (uint32_t)((lane >> 3) & 1) * 16;

    float acc[2][4][4];
    #pragma unroll
    for (int i = 0; i < 2; i++)
        #pragma unroll
        for (int j = 0; j < 4; j++)
            #pragma unroll
            for (int e = 0; e < 4; e++) acc[i][j][e] = 0.f;

    uint4 rp0; uint2 rv0;
    #define PLOAD(c) do { \
        rp0 = *(const uint4*)(aph + (size_t)(c)*8 + pp); \
        rv0 = *(const uint2*)(avh + (size_t)(c)*8 + vp); \
    } while (0)
    #define PSTAGE(bi) do { \
        *(uint4*)&Ph[bi][pr][pp] = rp0; \
        *(uint2*)&Vh[bi][vr][vp] = rv0; \
    } while (0)

    const int NC = CS / 16;            // 128 chunks
    PLOAD(0); PSTAGE(0); PLOAD(1);
    __syncthreads();

    for (int c = 0; c < NC; c++) {
        uint32_t cbP = (uint32_t)(c & 1) * BUFP;
        uint32_t cbV = (uint32_t)(c & 1) * BUFV;
        uint32_t bh[4][2];
        #pragma unroll
        for (int ntp = 0; ntp < 2; ntp++) {
            uint32_t nbase = (uint32_t)(wn*32 + ntp*16) * (RS*4);
            ldsm4(bh[2*ntp][0], bh[2*ntp][1], bh[2*ntp+1][0], bh[2*ntp+1][1], aVh + cbV + nbase + offB);
        }
        #pragma unroll
        for (int mt = 0; mt < 2; mt++) {
            uint32_t rbase = (uint32_t)(wm*32 + mt*16) * (RS*4);
            uint32_t a0, a1, a2, a3;
            ldsm4(a0, a1, a2, a3, aPh + cbP + rbase + offA);
            #pragma unroll
            for (int nt = 0; nt < 4; nt++)
                mma16h(acc[mt][nt][0], acc[mt][nt][1], acc[mt][nt][2], acc[mt][nt][3],
                       a0, a1, a2, a3, bh[nt][0], bh[nt][1]);
        }
        if (c + 1 < NC) {
            PSTAGE((c+1) & 1);
            if (c + 2 < NC) PLOAD(c+2);
        }
        __syncthreads();
    }
    #undef PLOAD
    #undef PSTAGE
    #pragma unroll
    for (int mt = 0; mt < 2; mt++) {
        #pragma unroll
        for (int half = 0; half < 2; half++) {
            int srow = s0 + wm*32 + mt*16 + qr + half*8;
            float ri = g_rsum[(size_t)z*CS + srow];
            const float* grow = g_gate + ((size_t)b*CS + srow)*CD + h*CDK;
            uint32_t* orow    = g_aop1 + ((size_t)b*CS + srow)*CDP + h*32;
            #pragma unroll
            for (int nt = 0; nt < 4; nt++) {
                int col = wn*32 + nt*8 + qc*2;
                float2 gg = *(const float2*)(grow + col);
                float o0 = acc[mt][nt][half*2+0] * ri * gg.x;
                float o1 = acc[mt][nt][half*2+1] * ri * gg.y;
                orow[col >> 1] = pack_h2(o0, o1);
            }
        }
    }
}

// ---------------- output projection: fp16 A single x fp16 Wo split ----------
__global__ __launch_bounds__(256, 2)
void out_gemm(const float* __restrict__ bo, float* __restrict__ C)
{
    __shared__ uint32_t Ah[2][128][RS];
    __shared__ uint32_t Bh[2][128][RS], Bl[2][128][RS];
    int tid = threadIdx.x, wid = tid >> 5, lane = tid & 31;
    int wm = wid & 1, wn = wid >> 1;
    int m0 = blockIdx.y * 128, n0 = blockIdx.x * 128;
    const uint32_t* Ag = g_aop1 + (size_t)m0 * CDP;
    const uint2*    Bg = g_wp[4] + (size_t)n0 * CDP;
    int lr = tid >> 2, kp = (tid & 3) * 2;
    int qr = lane >> 2, qc = lane & 3;

    const uint32_t BUF = 128*RS*4;
    uint32_t aAh = s2u(Ah), aBh = s2u(Bh), aBl = s2u(Bl);
    uint32_t offA = (uint32_t)(lane & 15) * (RS*4) + (uint32_t)((lane >> 4) & 1) * 16;
    uint32_t offB = (uint32_t)((lane & 7) + ((lane >> 4) & 1) * 8) * (RS*4)
                  + (uint32_t)((lane >> 3) & 1) * 16;

    float acc[4][4][4];
    #pragma unroll
    for (int i = 0; i < 4; i++)
        #pragma unroll
        for (int j = 0; j < 4; j++)
            #pragma unroll
            for (int e = 0; e < 4; e++) acc[i][j][e] = 0.f;

    uint2 rA0, rA1; uint4 rB0, rB1;
    #define OLOAD(c) do { \
        size_t o0_ = (size_t)lr*CDP + (size_t)(c)*8 + kp; \
        size_t o1_ = (size_t)(lr+64)*CDP + (size_t)(c)*8 + kp; \
        rA0 = *(const uint2*)(Ag + o0_); rA1 = *(const uint2*)(Ag + o1_); \
        rB0 = *(const uint4*)(Bg + o0_); rB1 = *(const uint4*)(Bg + o1_); \
    } while (0)
    #define OSTAGE(bi) do { \
        *(uint2*)&Ah[bi][lr][kp]    = rA0; \
        *(uint2*)&Ah[bi][lr+64][kp] = rA1; \
        *(uint2*)&Bh[bi][lr][kp]    = make_uint2(rB0.x, rB0.z); \
        *(uint2*)&Bl[bi][lr][kp]    = make_uint2(rB0.y, rB0.w); \
        *(uint2*)&Bh[bi][lr+64][kp] = make_uint2(rB1.x, rB1.z); \
        *(uint2*)&Bl[bi][lr+64][kp] = make_uint2(rB1.y, rB1.w); \
    } while (0)

    const int NC = CD / 16;
    OLOAD(0); OSTAGE(0); OLOAD(1);
    __syncthreads();

    for (int c = 0; c < NC; c++) {
        uint32_t cb = (uint32_t)(c & 1) * BUF;
        uint32_t bh[4][2], bl[4][2];
        #pragma unroll
        for (int ntp = 0; ntp < 2; ntp++) {
            uint32_t nbase = (uint32_t)(wn*32 + ntp*16) * (RS*4);
            ldsm4(bh[2*ntp][0], bh[2*ntp][1], bh[2*ntp+1][0], bh[2*ntp+1][1], aBh + cb + nbase + offB);
            ldsm4(bl[2*ntp][0], bl[2*ntp][1], bl[2*ntp+1][0], bl[2*ntp+1][1], aBl + cb + nbase + offB);
        }
        #pragma unroll
        for (int mt = 0; mt < 4; mt++) {
            uint32_t rbase = (uint32_t)(wm*64 + mt*16) * (RS*4);
            uint32_t a0, a1, a2, a3;
            ldsm4(a0, a1, a2, a3, aAh + cb + rbase + offA);
            #pragma unroll
            for (int nt = 0; nt < 4; nt++) {
                mma16h(acc[mt][nt][0], acc[mt][nt][1], acc[mt][nt][2], acc[mt][nt][3],
                       a0, a1, a2, a3, bh[nt][0], bh[nt][1]);
                mma16h(acc[mt][nt][0], acc[mt][nt][1], acc[mt][nt][2], acc[mt][nt][3],
                       a0, a1, a2, a3, bl[nt][0], bl[nt][1]);
            }
        }
        if (c + 1 < NC) {
            OSTAGE((c+1) & 1);
            if (c + 2 < NC) OLOAD(c+2);
        }
        __syncthreads();
    }
    #undef OLOAD
    #undef OSTAGE
    #pragma unroll
    for (int mt = 0; mt < 4; mt++) {
        int r = m0 + wm*64 + mt*16 + qr;
        #pragma unroll
        for (int nt = 0; nt < 4; nt++) {
            int col = n0 + wn*32 + nt*8 + qc*2;
            float b0 = bo[col], b1 = bo[col+1];
            *(float2*)(C + (size_t)r*CD + col) =
                make_float2(acc[mt][nt][0] + b0, acc[mt][nt][1] + b1);
            *(float2*)(C + (size_t)(r+8)*CD + col) =
                make_float2(acc[mt][nt][2] + b0, acc[mt][nt][3] + b1);
        }
    }
}

// ---------------- launch ----------------
extern "C" void kernel_launch(void* const* d_in, const int* in_sizes, int n_in,
                              void* d_out, int out_size)
{
    const float* x_q   = (const float*)d_in[0];
    const float* x_k   = (const float*)d_in[1];
    const float* Wq    = (const float*)d_in[2];
    const float* Wk    = (const float*)d_in[3];
    const float* Wv    = (const float*)d_in[4];
    const float* Wg    = (const float*)d_in[5];
    const float* bg    = (const float*)d_in[6];
    const float* Wo    = (const float*)d_in[7];
    const float* bo    = (const float*)d_in[8];
    const float* gamma = (const float*)d_in[9];
    const float* beta  = (const float*)d_in[10];
    float* out = (float*)d_out;

    const int SM_SCORES = 12*128*RS*4;   // 72KB
    cudaFuncSetAttribute(scores_stats,
                         cudaFuncAttributeMaxDynamicSharedMemorySize, SM_SCORES);

    // 1. LayerNorm (fp16 split) + weight split (fp16)
    ln_kernel<<<2*CM, 256>>>(x_q, x_k, gamma, beta);
    wsplit_kernel<<<dim3(CD*CDP/256, 5), 256>>>(Wq, Wk, Wv, Wg, Wo);

    // 2. All projections (q,k 3-MMA; v,gate 2-MMA)
    proj_all<<<dim3(CD/128, CM/128, 4), 256>>>(bg);

    // 3. Scores + stats: packed f32x2 exp epilogue, coalesced P stores
    scores_stats<<<dim3(CS/128, CS/128, CBH), 256, SM_SCORES>>>();

    // 4. Reduce partials -> reciprocal sums
    finalize_kernel<<<(2*CBH*CS)/256, 256>>>();

    // 5. V transpose with csum folded, single fp16
    vtrans_ci<<<dim3(CS/64, CBH), 256>>>();

    // 6. PV: single fp16 MMA per tile, occupancy 3
    pv_kernel<<<dim3(CS/128, CBH), 256>>>();

    // 7. Output projection + bias -> d_out
    out_gemm<<<dim3(CD/128, CM/128), 256>>>(bo, out);
}